// round 7
// baseline (speedup 1.0000x reference)
#include <cuda_runtime.h>
#include <cuda_bf16.h>
#include <math.h>

// ---------------- problem constants ----------------
#define SEQ     4096
#define BATCH   2
#define HID     768
#define NHEAD   12
#define HD      64
#define NLAYER  12
#define FFD     3072
#define WIN     256
#define NCHUNK  16
#define MTOK    8192          // BATCH * SEQ
#define NCLS    43

// ---------------- scratch (static device globals; allocation-free) ----------------
__device__ float g_h [MTOK * HID];
__device__ float g_q [MTOK * HID];
__device__ float g_k [MTOK * HID];
__device__ float g_v [MTOK * HID];
__device__ float g_a [MTOK * HID];
__device__ float g_t [MTOK * HID];
__device__ float g_ff[MTOK * FFD];

// ---------------- helpers ----------------
__device__ __forceinline__ float gelu_exact(float x) {
    return 0.5f * x * (1.0f + erff(x * 0.70710678118654752f));
}

// ============================================================================
// SGEMM: C[M,N] = A[M,K] @ B[K,N]  (+ epilogue)
// EPI 0: + bias
// EPI 1: (+ bias) * scale
// EPI 2: + bias + Res[M,N]
// EPI 3: gelu(+ bias)
// 128x128 tile, BK=8, 256 threads, 8x8 per thread. All dims divide exactly.
// ============================================================================
template <int EPI>
__global__ __launch_bounds__(256, 2)
void sgemm(const float* __restrict__ A, const float* __restrict__ B,
           const float* __restrict__ bias, const float* __restrict__ Res,
           float* __restrict__ C, int M, int N, int K, float scale)
{
    __shared__ float As[8][128];
    __shared__ float Bs[8][128];

    const int tid = threadIdx.x;
    const int bx = blockIdx.x, by = blockIdx.y;

    const int arow = tid >> 1;          // 0..127
    const int acol = (tid & 1) * 4;     // 0 or 4
    const int brow = tid >> 5;          // 0..7
    const int bcol = (tid & 31) * 4;    // 0..124

    const float* Aptr = A + (size_t)(by * 128 + arow) * K + acol;
    const float* Bptr = B + (size_t)brow * N + bx * 128 + bcol;

    const int tr = (tid >> 4) * 8;      // 0..120
    const int tc = (tid & 15) * 8;      // 0..120

    float acc[8][8];
#pragma unroll
    for (int i = 0; i < 8; i++)
#pragma unroll
        for (int j = 0; j < 8; j++) acc[i][j] = 0.f;

    for (int k0 = 0; k0 < K; k0 += 8) {
        float4 av = *(const float4*)Aptr;  Aptr += 8;
        float4 bv = *(const float4*)Bptr;  Bptr += (size_t)8 * N;

        As[acol + 0][arow] = av.x;
        As[acol + 1][arow] = av.y;
        As[acol + 2][arow] = av.z;
        As[acol + 3][arow] = av.w;
        *(float4*)&Bs[brow][bcol] = bv;
        __syncthreads();

#pragma unroll
        for (int kk = 0; kk < 8; kk++) {
            float ar[8], br[8];
#pragma unroll
            for (int i = 0; i < 8; i++) ar[i] = As[kk][tr + i];
#pragma unroll
            for (int j = 0; j < 8; j++) br[j] = Bs[kk][tc + j];
#pragma unroll
            for (int i = 0; i < 8; i++)
#pragma unroll
                for (int j = 0; j < 8; j++)
                    acc[i][j] = fmaf(ar[i], br[j], acc[i][j]);
        }
        __syncthreads();
    }

    // epilogue
#pragma unroll
    for (int i = 0; i < 8; i++) {
        const size_t row = (size_t)(by * 128 + tr + i);
        float* crow = C + row * (size_t)N;
        const float* rrow = (EPI == 2) ? (Res + row * (size_t)N) : nullptr;
#pragma unroll
        for (int j = 0; j < 8; j += 4) {
            const int col = bx * 128 + tc + j;
            float4 o;
            o.x = acc[i][j + 0] + bias[col + 0];
            o.y = acc[i][j + 1] + bias[col + 1];
            o.z = acc[i][j + 2] + bias[col + 2];
            o.w = acc[i][j + 3] + bias[col + 3];
            if (EPI == 1) { o.x *= scale; o.y *= scale; o.z *= scale; o.w *= scale; }
            if (EPI == 2) {
                float4 rv = *(const float4*)(rrow + col);
                o.x += rv.x; o.y += rv.y; o.z += rv.z; o.w += rv.w;
            }
            if (EPI == 3) {
                o.x = gelu_exact(o.x); o.y = gelu_exact(o.y);
                o.z = gelu_exact(o.z); o.w = gelu_exact(o.w);
            }
            *(float4*)(crow + col) = o;
        }
    }
}

// ============================================================================
// Embedding + LayerNorm: one block per token row (256 threads, 3 elems/thread)
// ============================================================================
__global__ void embed_ln_kernel(const int* __restrict__ ids,
                                const float* __restrict__ we,
                                const float* __restrict__ pe,
                                const float* __restrict__ te,
                                const float* __restrict__ g,
                                const float* __restrict__ be,
                                float* __restrict__ out)
{
    __shared__ float red[256];
    const int row = blockIdx.x;           // 0..8191
    const int s = row & (SEQ - 1);
    const int tid = threadIdx.x;
    const int id = ids[row];

    float x[3];
#pragma unroll
    for (int i = 0; i < 3; i++) {
        const int j = tid + i * 256;
        x[i] = we[(size_t)id * HID + j] + pe[(size_t)(s + 2) * HID + j] + te[j];
    }
    float sum = x[0] + x[1] + x[2];
    red[tid] = sum; __syncthreads();
    for (int st = 128; st > 0; st >>= 1) { if (tid < st) red[tid] += red[tid + st]; __syncthreads(); }
    const float mean = red[0] * (1.f / HID);
    __syncthreads();

    float vs = 0.f;
#pragma unroll
    for (int i = 0; i < 3; i++) { float d = x[i] - mean; vs += d * d; }
    red[tid] = vs; __syncthreads();
    for (int st = 128; st > 0; st >>= 1) { if (tid < st) red[tid] += red[tid + st]; __syncthreads(); }
    const float rstd = rsqrtf(red[0] * (1.f / HID) + 1e-5f);

#pragma unroll
    for (int i = 0; i < 3; i++) {
        const int j = tid + i * 256;
        out[(size_t)row * HID + j] = (x[i] - mean) * rstd * g[j] + be[j];
    }
}

// ============================================================================
// LayerNorm: out = LN(in) with gamma/beta. One block per row.
// ============================================================================
__global__ void ln_kernel(const float* __restrict__ in,
                          const float* __restrict__ g,
                          const float* __restrict__ be,
                          float* __restrict__ out)
{
    __shared__ float red[256];
    const int row = blockIdx.x;
    const int tid = threadIdx.x;

    float x[3];
#pragma unroll
    for (int i = 0; i < 3; i++) x[i] = in[(size_t)row * HID + tid + i * 256];

    float sum = x[0] + x[1] + x[2];
    red[tid] = sum; __syncthreads();
    for (int st = 128; st > 0; st >>= 1) { if (tid < st) red[tid] += red[tid + st]; __syncthreads(); }
    const float mean = red[0] * (1.f / HID);
    __syncthreads();

    float vs = 0.f;
#pragma unroll
    for (int i = 0; i < 3; i++) { float d = x[i] - mean; vs += d * d; }
    red[tid] = vs; __syncthreads();
    for (int st = 128; st > 0; st >>= 1) { if (tid < st) red[tid] += red[tid + st]; __syncthreads(); }
    const float rstd = rsqrtf(red[0] * (1.f / HID) + 1e-5f);

#pragma unroll
    for (int i = 0; i < 3; i++) {
        const int j = tid + i * 256;
        out[(size_t)row * HID + j] = (x[i] - mean) * rstd * g[j] + be[j];
    }
}

// ============================================================================
// Sliding-window attention.
// grid = (NCHUNK, NHEAD, BATCH); block = 256 (one thread per query in chunk).
// q already scaled by 1/sqrt(D). Online softmax over 24 tiles of 32 keys.
// Query r attends keys tk in [r, r+2W] of the 3W window, key must be in-range
// and attention_mask != 0.
// ============================================================================
__global__ __launch_bounds__(256, 1)
void attn_kernel(const float* __restrict__ qg, const float* __restrict__ kg,
                 const float* __restrict__ vg, const int* __restrict__ amask,
                 float* __restrict__ outp)
{
    __shared__ float ks [32][64];
    __shared__ float vsm[32][64];
    __shared__ int   kval[32];

    const int c  = blockIdx.x;
    const int hh = blockIdx.y;
    const int b  = blockIdx.z;
    const int r  = threadIdx.x;

    const size_t rowoff = ((size_t)(b * SEQ + c * WIN + r)) * HID + hh * HD;

    float qr[64];
#pragma unroll
    for (int i = 0; i < 16; i++) {
        float4 tq = *(const float4*)(qg + rowoff + i * 4);
        qr[4*i] = tq.x; qr[4*i+1] = tq.y; qr[4*i+2] = tq.z; qr[4*i+3] = tq.w;
    }
    float o[64];
#pragma unroll
    for (int i = 0; i < 64; i++) o[i] = 0.f;
    float mrun = -1e30f, lrun = 0.f;

    const int lr = r >> 3;          // 0..31: key row this thread loads
    const int lc = (r & 7) * 8;     // col start

    for (int t0 = 0; t0 < 3 * WIN; t0 += 32) {
        const int pos = (c - 1) * WIN + t0 + lr;     // global key position
        const bool vld = (pos >= 0) && (pos < SEQ) && (amask[b * SEQ + pos] != 0);
        const float* kp = kg + ((size_t)(b * SEQ + pos)) * HID + hh * HD + lc;
        const float* vp = vg + ((size_t)(b * SEQ + pos)) * HID + hh * HD + lc;
        const float4 z = make_float4(0.f, 0.f, 0.f, 0.f);
        float4 ka = vld ? *(const float4*)(kp)     : z;
        float4 kb = vld ? *(const float4*)(kp + 4) : z;
        float4 va = vld ? *(const float4*)(vp)     : z;
        float4 vb = vld ? *(const float4*)(vp + 4) : z;

        __syncthreads();
        *(float4*)&ks [lr][lc]     = ka;
        *(float4*)&ks [lr][lc + 4] = kb;
        *(float4*)&vsm[lr][lc]     = va;
        *(float4*)&vsm[lr][lc + 4] = vb;
        if ((r & 7) == 0) kval[lr] = vld ? 1 : 0;
        __syncthreads();

        float sc[32];
        float tmax = -1e30f;
#pragma unroll
        for (int t = 0; t < 32; t++) {
            const int tk = t0 + t;
            float s_ = -1e30f;
            if ((tk >= r) && (tk <= r + 2 * WIN) && kval[t]) {
                s_ = 0.f;
#pragma unroll
                for (int i = 0; i < 16; i++) {
                    float4 kk = *(const float4*)&ks[t][4 * i];
                    s_ = fmaf(qr[4*i],   kk.x, s_);
                    s_ = fmaf(qr[4*i+1], kk.y, s_);
                    s_ = fmaf(qr[4*i+2], kk.z, s_);
                    s_ = fmaf(qr[4*i+3], kk.w, s_);
                }
            }
            sc[t] = s_;
            tmax = fmaxf(tmax, s_);
        }
        if (tmax > mrun) {
            const float corr = __expf(mrun - tmax);
            mrun = tmax;
            lrun *= corr;
#pragma unroll
            for (int i = 0; i < 64; i++) o[i] *= corr;
        }
#pragma unroll
        for (int t = 0; t < 32; t++) {
            if (sc[t] > -1e29f) {
                const float p = __expf(sc[t] - mrun);
                lrun += p;
#pragma unroll
                for (int i = 0; i < 16; i++) {
                    float4 vv = *(const float4*)&vsm[t][4 * i];
                    o[4*i]   = fmaf(p, vv.x, o[4*i]);
                    o[4*i+1] = fmaf(p, vv.y, o[4*i+1]);
                    o[4*i+2] = fmaf(p, vv.z, o[4*i+2]);
                    o[4*i+3] = fmaf(p, vv.w, o[4*i+3]);
                }
            }
        }
    }

    const float inv = 1.f / lrun;
#pragma unroll
    for (int i = 0; i < 16; i++) {
        float4 tv;
        tv.x = o[4*i] * inv; tv.y = o[4*i+1] * inv;
        tv.z = o[4*i+2] * inv; tv.w = o[4*i+3] * inv;
        *(float4*)(outp + rowoff + i * 4) = tv;
    }
}

// ============================================================================
// Classifier head: pooled = h[:,0]; out = relu(pooled @ W1 + b1) @ W2 + b2
// grid = BATCH, block = 512
// ============================================================================
__global__ void cls_kernel(const float* __restrict__ h,
                           const float* __restrict__ w1, const float* __restrict__ b1,
                           const float* __restrict__ w2, const float* __restrict__ b2,
                           float* __restrict__ out)
{
    __shared__ float pooled[HID];
    __shared__ float x[512];
    const int b = blockIdx.x;
    const int tid = threadIdx.x;
    const float* hp = h + (size_t)b * SEQ * HID;

    for (int j = tid; j < HID; j += 512) pooled[j] = hp[j];
    __syncthreads();

    {
        float acc = b1[tid];
        for (int k = 0; k < HID; k++) acc = fmaf(pooled[k], w1[(size_t)k * 512 + tid], acc);
        x[tid] = fmaxf(acc, 0.f);
    }
    __syncthreads();

    if (tid < NCLS) {
        float acc = b2[tid];
        for (int k = 0; k < 512; k++) acc = fmaf(x[k], w2[(size_t)k * NCLS + tid], acc);
        out[b * NCLS + tid] = acc;
    }
}

// ============================================================================
// kernel_launch
// ============================================================================
extern "C" void kernel_launch(void* const* d_in, const int* in_sizes, int n_in,
                              void* d_out, int out_size)
{
    (void)in_sizes; (void)n_in; (void)out_size;

    const int*   ids   = (const int*)  d_in[0];
    const int*   amask = (const int*)  d_in[1];
    const float* we    = (const float*)d_in[2];
    const float* pe    = (const float*)d_in[3];
    const float* te    = (const float*)d_in[4];
    const float* elg   = (const float*)d_in[5];
    const float* elb   = (const float*)d_in[6];
    const float* Wq    = (const float*)d_in[7];
    const float* bq    = (const float*)d_in[8];
    const float* Wk    = (const float*)d_in[9];
    const float* bk    = (const float*)d_in[10];
    const float* Wv    = (const float*)d_in[11];
    const float* bv    = (const float*)d_in[12];
    const float* Wo    = (const float*)d_in[13];
    const float* bo    = (const float*)d_in[14];
    const float* g1    = (const float*)d_in[15];
    const float* b1    = (const float*)d_in[16];
    const float* Wi    = (const float*)d_in[17];
    const float* bi    = (const float*)d_in[18];
    const float* Wo2   = (const float*)d_in[19];
    const float* bo2   = (const float*)d_in[20];
    const float* g2    = (const float*)d_in[21];
    const float* b2    = (const float*)d_in[22];
    const float* cw1   = (const float*)d_in[23];
    const float* cb1   = (const float*)d_in[24];
    const float* cw2   = (const float*)d_in[25];
    const float* cb2   = (const float*)d_in[26];
    float* out = (float*)d_out;

    float *h, *q, *k, *v, *a, *t, *ff;
    cudaGetSymbolAddress((void**)&h,  g_h);
    cudaGetSymbolAddress((void**)&q,  g_q);
    cudaGetSymbolAddress((void**)&k,  g_k);
    cudaGetSymbolAddress((void**)&v,  g_v);
    cudaGetSymbolAddress((void**)&a,  g_a);
    cudaGetSymbolAddress((void**)&t,  g_t);
    cudaGetSymbolAddress((void**)&ff, g_ff);

    embed_ln_kernel<<<MTOK, 256>>>(ids, we, pe, te, elg, elb, h);

    const dim3 g768 (HID / 128, MTOK / 128);   // (6, 64)
    const dim3 g3072(FFD / 128, MTOK / 128);   // (24, 64)
    const dim3 ga(NCHUNK, NHEAD, BATCH);
    const float qscale = 0.125f;               // 1/sqrt(64)

    for (int l = 0; l < NLAYER; l++) {
        const size_t wHH = (size_t)l * HID * HID;
        const size_t wHF = (size_t)l * HID * FFD;

        sgemm<1><<<g768, 256>>>(h, Wq + wHH, bq + l * HID, nullptr, q, MTOK, HID, HID, qscale);
        sgemm<0><<<g768, 256>>>(h, Wk + wHH, bk + l * HID, nullptr, k, MTOK, HID, HID, 1.f);
        sgemm<0><<<g768, 256>>>(h, Wv + wHH, bv + l * HID, nullptr, v, MTOK, HID, HID, 1.f);

        attn_kernel<<<ga, 256>>>(q, k, v, amask, a);

        sgemm<2><<<g768, 256>>>(a, Wo + wHH, bo + l * HID, h, t, MTOK, HID, HID, 1.f);
        ln_kernel<<<MTOK, 256>>>(t, g1 + l * HID, b1 + l * HID, h);

        sgemm<3><<<g3072, 256>>>(h, Wi + wHF, bi + l * FFD, nullptr, ff, MTOK, FFD, HID, 1.f);
        sgemm<2><<<g768, 256>>>(ff, Wo2 + wHF, bo2 + l * HID, h, t, MTOK, HID, FFD, 1.f);
        ln_kernel<<<MTOK, 256>>>(t, g2 + l * HID, b2 + l * HID, h);
    }

    cls_kernel<<<BATCH, 512>>>(h, cw1, cb1, cw2, cb2, out);
}

// round 12
// speedup vs baseline: 1.9976x; 1.9976x over previous
#include <cuda_runtime.h>
#include <cuda_bf16.h>
#include <math.h>
#include <stdint.h>

// ---------------- problem constants ----------------
#define SEQ     4096
#define BATCH   2
#define HID     768
#define NHEAD   12
#define HD      64
#define NLAYER  12
#define FFD     3072
#define WIN     256
#define NCHUNK  16
#define MTOK    8192          // BATCH * SEQ
#define NCLS    43

#define WSLOT_HH 589824       // 768*768
#define WSLOT_HF 2359296      // 768*3072
#define WLAYER   7077888      // 4*HH + 2*HF

// ---------------- scratch (static device globals; allocation-free) ----------------
__device__ float g_h[MTOK*HID];
__device__ float g_t[MTOK*HID];
__device__ float g_q[MTOK*HID];
__device__ float g_k[MTOK*HID];
__device__ float g_v[MTOK*HID];
__device__ __nv_bfloat16 g_hhi[MTOK*HID];
__device__ __nv_bfloat16 g_hlo[MTOK*HID];
__device__ __nv_bfloat16 g_ahi[MTOK*HID];
__device__ __nv_bfloat16 g_alo[MTOK*HID];
__device__ __nv_bfloat16 g_fhi[MTOK*FFD];
__device__ __nv_bfloat16 g_flo[MTOK*FFD];
__device__ __nv_bfloat16 g_whi[(size_t)NLAYER*WLAYER];
__device__ __nv_bfloat16 g_wlo[(size_t)NLAYER*WLAYER];

// ---------------- PTX helpers (sm_80-class only: portable to sm_103 base) ----
__device__ __forceinline__ uint32_t smem_u32(const void* p) {
    uint32_t a;
    asm("{ .reg .u64 t; cvta.to.shared.u64 t, %1; cvt.u32.u64 %0, t; }" : "=r"(a) : "l"(p));
    return a;
}
__device__ __forceinline__ void cpasync16(uint32_t s, const void* g) {
    asm volatile("cp.async.cg.shared.global [%0], [%1], 16;" :: "r"(s), "l"(g));
}
__device__ __forceinline__ void cp_commit() {
    asm volatile("cp.async.commit_group;" ::: "memory");
}
__device__ __forceinline__ void cp_wait1() {
    asm volatile("cp.async.wait_group 1;" ::: "memory");
}
__device__ __forceinline__ void ldm_x4(uint32_t* r, uint32_t a) {
    asm volatile("ldmatrix.sync.aligned.m8n8.x4.shared.b16 {%0,%1,%2,%3}, [%4];"
        : "=r"(r[0]), "=r"(r[1]), "=r"(r[2]), "=r"(r[3]) : "r"(a));
}
__device__ __forceinline__ void mma16816(float* c, const uint32_t* a, const uint32_t* b) {
    asm volatile(
        "mma.sync.aligned.m16n8k16.row.col.f32.bf16.bf16.f32 "
        "{%0,%1,%2,%3}, {%4,%5,%6,%7}, {%8,%9}, {%0,%1,%2,%3};"
        : "+f"(c[0]), "+f"(c[1]), "+f"(c[2]), "+f"(c[3])
        : "r"(a[0]), "r"(a[1]), "r"(a[2]), "r"(a[3]), "r"(b[0]), "r"(b[1]));
}

__device__ __forceinline__ uint32_t swz(uint32_t b) { return b ^ ((b >> 3) & 0x70); }

__device__ __forceinline__ float gelu_exact(float x) {
    return 0.5f * x * (1.0f + erff(x * 0.70710678118654752f));
}
__device__ __forceinline__ uint32_t packbf2(float a, float b) {
    __nv_bfloat162 t = __floats2bfloat162_rn(a, b);
    return *reinterpret_cast<uint32_t*>(&t);
}
__device__ __forceinline__ float bf_hi(float x) {
    return __bfloat162float(__float2bfloat16(x));
}

// ============================================================================
// Weight prep: W[K][N] fp32  ->  hi/lo[N][K] bf16 (transpose + split)
// grid (N/32, K/32), block (32, 8)
// ============================================================================
__global__ void wprep(const float* __restrict__ W, __nv_bfloat16* __restrict__ hi,
                      __nv_bfloat16* __restrict__ lo, int K, int N)
{
    __shared__ float t[32][33];
    const int k0 = blockIdx.y * 32, n0 = blockIdx.x * 32;
    const int tx = threadIdx.x, ty = threadIdx.y;
#pragma unroll
    for (int i = 0; i < 4; i++)
        t[ty + i*8][tx] = W[(size_t)(k0 + ty + i*8) * N + n0 + tx];
    __syncthreads();
#pragma unroll
    for (int i = 0; i < 4; i++) {
        float x = t[tx][ty + i*8];
        __nv_bfloat16 h = __float2bfloat16(x);
        __nv_bfloat16 l = __float2bfloat16(x - __bfloat162float(h));
        size_t o = (size_t)(n0 + ty + i*8) * K + k0 + tx;
        hi[o] = h; lo[o] = l;
    }
}

// ============================================================================
// mma.sync bf16x3 GEMM: C[M,N] = A[M,K] @ B^T[N,K].
// A: Ahi/Alo [M][K] bf16 K-major; B: Bhi/Blo [N][K] bf16 K-major.
// 128x128 tile, BK=64, 2-stage cp.async double buffer, 256 threads (8 warps).
// Warp tile 32m x 64n. 3 MMA passes: Ah*Bh + Ah*Bl + Al*Bh (fp32 accum).
// EPI: 0 fp32(+bias), 1 (+bias)*scale, 2 (+bias)+Res, 3 gelu -> bf16 hi/lo
// ============================================================================
#define STG_BYTES   65536
#define DSMEM_BYTES (1024 + 2*STG_BYTES)
#define OFF_AHI 0
#define OFF_ALO 16384
#define OFF_BHI 32768
#define OFF_BLO 49152

template <int EPI>
__global__ __launch_bounds__(256, 1)
void tgemm(const __nv_bfloat16* __restrict__ Ahi, const __nv_bfloat16* __restrict__ Alo,
           const __nv_bfloat16* __restrict__ Bhi, const __nv_bfloat16* __restrict__ Blo,
           const float* __restrict__ bias, const float* __restrict__ Res,
           float* __restrict__ Cf, __nv_bfloat16* __restrict__ Chi, __nv_bfloat16* __restrict__ Clo,
           int K, int N, float scale)
{
    extern __shared__ char dsm[];
    char* sgen = (char*)((((uintptr_t)dsm) + 1023) & ~(uintptr_t)1023);
    const uint32_t sb = smem_u32(sgen);

    const int tid = threadIdx.x;
    const int wid = tid >> 5;
    const int lane = tid & 31;
    const int m0 = blockIdx.y * 128;
    const int n0 = blockIdx.x * 128;

    // ---- producer addressing (cp.async, 16B) ----
    const int lrow  = tid >> 1;          // 0..127
    const int lhalf = tid & 1;           // k 0-31 / 32-63
    const size_t aoff = (size_t)(m0 + lrow) * K + lhalf * 32;
    const size_t boff = (size_t)(n0 + lrow) * K + lhalf * 32;
    uint32_t so[4];
#pragma unroll
    for (int g = 0; g < 4; g++)
        so[g] = swz((uint32_t)(lrow * 128 + (lhalf * 32 + g * 8) * 2));

    // ---- consumer (mma) lane addressing ----
    const int wm = wid & 3;              // 4 m-groups of 32
    const int wn = wid >> 2;             // 2 n-groups of 64
    const int xr = (lane & 7) * 16;      // swizzle XOR within 128B row
    const int aKoff = (lane & 16) ? 16 : 0;
    const int bKoff = (lane & 8)  ? 16 : 0;
    const int aRowIn = (lane & 7) + ((lane & 8)  ? 8 : 0);
    const int bRowIn = (lane & 7) + ((lane & 16) ? 8 : 0);
    uint32_t aRB[2], bRB[4];
#pragma unroll
    for (int mt = 0; mt < 2; mt++) aRB[mt] = (uint32_t)(wm*32 + mt*16 + aRowIn) * 128;
#pragma unroll
    for (int p = 0; p < 4; p++)    bRB[p]  = (uint32_t)(wn*64 + p*16 + bRowIn) * 128;

    float acc[2][8][4];
#pragma unroll
    for (int mt = 0; mt < 2; mt++)
#pragma unroll
        for (int nt = 0; nt < 8; nt++)
#pragma unroll
            for (int r = 0; r < 4; r++) acc[mt][nt][r] = 0.f;

    const int NC = K >> 6;

    // issue a chunk's copies into a stage
    auto issue = [&](int ck, int s) {
        const size_t kb = (size_t)ck * 64;
        const uint32_t st = sb + 1024 + s * STG_BYTES;
#pragma unroll
        for (int g = 0; g < 4; g++) {
            const uint32_t o = so[g];
            const size_t gofs = kb + g * 8;
            cpasync16(st + OFF_AHI + o, Ahi + aoff + gofs);
            cpasync16(st + OFF_ALO + o, Alo + aoff + gofs);
            cpasync16(st + OFF_BHI + o, Bhi + boff + gofs);
            cpasync16(st + OFF_BLO + o, Blo + boff + gofs);
        }
    };

    issue(0, 0); cp_commit();
    issue(1, 1); cp_commit();

    for (int ck = 0; ck < NC; ck++) {
        const int s = ck & 1;
        cp_wait1();
        __syncthreads();

        const uint32_t st = sb + 1024 + s * STG_BYTES;
#pragma unroll
        for (int ks = 0; ks < 4; ks++) {
            const uint32_t kA = (uint32_t)((ks*32 + aKoff) ^ xr);
            const uint32_t kB = (uint32_t)((ks*32 + bKoff) ^ xr);
            uint32_t Ah[2][4], Al[2][4];
#pragma unroll
            for (int mt = 0; mt < 2; mt++) {
                const uint32_t o = aRB[mt] + kA;
                ldm_x4(Ah[mt], st + OFF_AHI + o);
                ldm_x4(Al[mt], st + OFF_ALO + o);
            }
            uint32_t Bh[4][4], Bl[4][4];
#pragma unroll
            for (int p = 0; p < 4; p++) {
                const uint32_t o = bRB[p] + kB;
                ldm_x4(Bh[p], st + OFF_BHI + o);
                ldm_x4(Bl[p], st + OFF_BLO + o);
            }
#pragma unroll
            for (int mt = 0; mt < 2; mt++)
#pragma unroll
                for (int p = 0; p < 4; p++)
#pragma unroll
                    for (int hf = 0; hf < 2; hf++) {
                        float* c = acc[mt][p*2 + hf];
                        mma16816(c, Ah[mt], &Bh[p][hf*2]);
                        mma16816(c, Ah[mt], &Bl[p][hf*2]);
                        mma16816(c, Al[mt], &Bh[p][hf*2]);
                    }
        }
        __syncthreads();
        if (ck + 2 < NC) issue(ck + 2, s);
        cp_commit();
    }

    // ---- epilogue ----
    const int r0 = lane >> 2;            // 0..7
    const int cN = (lane & 3) * 2;
    const int mBase = m0 + wm * 32;
    const int nBase = n0 + wn * 64;

#pragma unroll
    for (int mt = 0; mt < 2; mt++) {
#pragma unroll
        for (int nt = 0; nt < 8; nt++) {
            const int n = nBase + nt * 8 + cN;
            const float bx = bias[n], by = bias[n + 1];
#pragma unroll
            for (int hf = 0; hf < 2; hf++) {
                const int m = mBase + mt * 16 + r0 + hf * 8;
                float vx = acc[mt][nt][hf*2 + 0] + bx;
                float vy = acc[mt][nt][hf*2 + 1] + by;
                if (EPI == 1) { vx *= scale; vy *= scale; }
                if (EPI == 2) {
                    const float2 rv = *(const float2*)(Res + (size_t)m * N + n);
                    vx += rv.x; vy += rv.y;
                }
                if (EPI == 3) {
                    vx = gelu_exact(vx); vy = gelu_exact(vy);
                    const size_t o = (size_t)m * N + n;
                    *(uint32_t*)(Chi + o) = packbf2(vx, vy);
                    *(uint32_t*)(Clo + o) = packbf2(vx - bf_hi(vx), vy - bf_hi(vy));
                } else {
                    float2 ov; ov.x = vx; ov.y = vy;
                    *(float2*)(Cf + (size_t)m * N + n) = ov;
                }
            }
        }
    }
}

// ============================================================================
// Embedding + LayerNorm -> fp32 h + bf16 hi/lo
// ============================================================================
__global__ void embed_ln_kernel(const int* __restrict__ ids,
                                const float* __restrict__ we, const float* __restrict__ pe,
                                const float* __restrict__ te, const float* __restrict__ g,
                                const float* __restrict__ be, float* __restrict__ out,
                                __nv_bfloat16* __restrict__ ohi, __nv_bfloat16* __restrict__ olo)
{
    __shared__ float red[256];
    const int row = blockIdx.x;
    const int s = row & (SEQ - 1);
    const int tid = threadIdx.x;
    const int id = ids[row];

    float x[3];
#pragma unroll
    for (int i = 0; i < 3; i++) {
        const int j = tid + i * 256;
        x[i] = we[(size_t)id * HID + j] + pe[(size_t)(s + 2) * HID + j] + te[j];
    }
    float sum = x[0] + x[1] + x[2];
    red[tid] = sum; __syncthreads();
    for (int st = 128; st > 0; st >>= 1) { if (tid < st) red[tid] += red[tid + st]; __syncthreads(); }
    const float mean = red[0] * (1.f / HID);
    __syncthreads();
    float vs = 0.f;
#pragma unroll
    for (int i = 0; i < 3; i++) { float dd = x[i] - mean; vs += dd * dd; }
    red[tid] = vs; __syncthreads();
    for (int st = 128; st > 0; st >>= 1) { if (tid < st) red[tid] += red[tid + st]; __syncthreads(); }
    const float rstd = rsqrtf(red[0] * (1.f / HID) + 1e-5f);

#pragma unroll
    for (int i = 0; i < 3; i++) {
        const int j = tid + i * 256;
        const float y = (x[i] - mean) * rstd * g[j] + be[j];
        const size_t o = (size_t)row * HID + j;
        out[o] = y;
        __nv_bfloat16 h = __float2bfloat16(y);
        ohi[o] = h;
        olo[o] = __float2bfloat16(y - __bfloat162float(h));
    }
}

// ============================================================================
// LayerNorm -> fp32 + bf16 hi/lo
// ============================================================================
__global__ void ln_kernel(const float* __restrict__ in, const float* __restrict__ g,
                          const float* __restrict__ be, float* __restrict__ out,
                          __nv_bfloat16* __restrict__ ohi, __nv_bfloat16* __restrict__ olo)
{
    __shared__ float red[256];
    const int row = blockIdx.x;
    const int tid = threadIdx.x;

    float x[3];
#pragma unroll
    for (int i = 0; i < 3; i++) x[i] = in[(size_t)row * HID + tid + i * 256];
    float sum = x[0] + x[1] + x[2];
    red[tid] = sum; __syncthreads();
    for (int st = 128; st > 0; st >>= 1) { if (tid < st) red[tid] += red[tid + st]; __syncthreads(); }
    const float mean = red[0] * (1.f / HID);
    __syncthreads();
    float vs = 0.f;
#pragma unroll
    for (int i = 0; i < 3; i++) { float dd = x[i] - mean; vs += dd * dd; }
    red[tid] = vs; __syncthreads();
    for (int st = 128; st > 0; st >>= 1) { if (tid < st) red[tid] += red[tid + st]; __syncthreads(); }
    const float rstd = rsqrtf(red[0] * (1.f / HID) + 1e-5f);

#pragma unroll
    for (int i = 0; i < 3; i++) {
        const int j = tid + i * 256;
        const float y = (x[i] - mean) * rstd * g[j] + be[j];
        const size_t o = (size_t)row * HID + j;
        out[o] = y;
        __nv_bfloat16 h = __float2bfloat16(y);
        ohi[o] = h;
        olo[o] = __float2bfloat16(y - __bfloat162float(h));
    }
}

// ============================================================================
// Sliding-window attention; output split to bf16 hi/lo.
// ============================================================================
__global__ __launch_bounds__(256, 1)
void attn_kernel(const float* __restrict__ qg, const float* __restrict__ kg,
                 const float* __restrict__ vg, const int* __restrict__ amask,
                 __nv_bfloat16* __restrict__ ohi, __nv_bfloat16* __restrict__ olo)
{
    __shared__ float ks [32][64];
    __shared__ float vsm[32][64];
    __shared__ int   kval[32];

    const int c  = blockIdx.x;
    const int hh = blockIdx.y;
    const int b  = blockIdx.z;
    const int r  = threadIdx.x;

    const size_t rowoff = ((size_t)(b * SEQ + c * WIN + r)) * HID + hh * HD;

    float qr[64];
#pragma unroll
    for (int i = 0; i < 16; i++) {
        float4 tq = *(const float4*)(qg + rowoff + i * 4);
        qr[4*i] = tq.x; qr[4*i+1] = tq.y; qr[4*i+2] = tq.z; qr[4*i+3] = tq.w;
    }
    float o[64];
#pragma unroll
    for (int i = 0; i < 64; i++) o[i] = 0.f;
    float mrun = -1e30f, lrun = 0.f;

    const int lr = r >> 3;
    const int lc = (r & 7) * 8;

    for (int t0 = 0; t0 < 3 * WIN; t0 += 32) {
        const int pos = (c - 1) * WIN + t0 + lr;
        const bool vld = (pos >= 0) && (pos < SEQ) && (amask[b * SEQ + pos] != 0);
        const float* kp = kg + ((size_t)(b * SEQ + pos)) * HID + hh * HD + lc;
        const float* vp = vg + ((size_t)(b * SEQ + pos)) * HID + hh * HD + lc;
        const float4 z = make_float4(0.f, 0.f, 0.f, 0.f);
        float4 ka = vld ? *(const float4*)(kp)     : z;
        float4 kb = vld ? *(const float4*)(kp + 4) : z;
        float4 va = vld ? *(const float4*)(vp)     : z;
        float4 vb = vld ? *(const float4*)(vp + 4) : z;

        __syncthreads();
        *(float4*)&ks [lr][lc]     = ka;
        *(float4*)&ks [lr][lc + 4] = kb;
        *(float4*)&vsm[lr][lc]     = va;
        *(float4*)&vsm[lr][lc + 4] = vb;
        if ((r & 7) == 0) kval[lr] = vld ? 1 : 0;
        __syncthreads();

        float sc[32];
        float tmax = -1e30f;
#pragma unroll
        for (int t = 0; t < 32; t++) {
            const int tk = t0 + t;
            float s_ = -1e30f;
            if ((tk >= r) && (tk <= r + 2 * WIN) && kval[t]) {
                s_ = 0.f;
#pragma unroll
                for (int i = 0; i < 16; i++) {
                    float4 kk = *(const float4*)&ks[t][4 * i];
                    s_ = fmaf(qr[4*i],   kk.x, s_);
                    s_ = fmaf(qr[4*i+1], kk.y, s_);
                    s_ = fmaf(qr[4*i+2], kk.z, s_);
                    s_ = fmaf(qr[4*i+3], kk.w, s_);
                }
            }
            sc[t] = s_;
            tmax = fmaxf(tmax, s_);
        }
        if (tmax > mrun) {
            const float corr = __expf(mrun - tmax);
            mrun = tmax;
            lrun *= corr;
#pragma unroll
            for (int i = 0; i < 64; i++) o[i] *= corr;
        }
#pragma unroll
        for (int t = 0; t < 32; t++) {
            if (sc[t] > -1e29f) {
                const float p = __expf(sc[t] - mrun);
                lrun += p;
#pragma unroll
                for (int i = 0; i < 16; i++) {
                    float4 vv = *(const float4*)&vsm[t][4 * i];
                    o[4*i]   = fmaf(p, vv.x, o[4*i]);
                    o[4*i+1] = fmaf(p, vv.y, o[4*i+1]);
                    o[4*i+2] = fmaf(p, vv.z, o[4*i+2]);
                    o[4*i+3] = fmaf(p, vv.w, o[4*i+3]);
                }
            }
        }
    }

    const float inv = 1.f / lrun;
#pragma unroll
    for (int i = 0; i < 8; i++) {
        float v[8];
#pragma unroll
        for (int j = 0; j < 8; j++) v[j] = o[i * 8 + j] * inv;
        uint4 hw, lw;
        hw.x = packbf2(v[0], v[1]); hw.y = packbf2(v[2], v[3]);
        hw.z = packbf2(v[4], v[5]); hw.w = packbf2(v[6], v[7]);
        float rr[8];
#pragma unroll
        for (int j = 0; j < 8; j++) rr[j] = v[j] - bf_hi(v[j]);
        lw.x = packbf2(rr[0], rr[1]); lw.y = packbf2(rr[2], rr[3]);
        lw.z = packbf2(rr[4], rr[5]); lw.w = packbf2(rr[6], rr[7]);
        *(uint4*)(ohi + rowoff + i * 8) = hw;
        *(uint4*)(olo + rowoff + i * 8) = lw;
    }
}

// ============================================================================
// Classifier head
// ============================================================================
__global__ void cls_kernel(const float* __restrict__ h,
                           const float* __restrict__ w1, const float* __restrict__ b1,
                           const float* __restrict__ w2, const float* __restrict__ b2,
                           float* __restrict__ out)
{
    __shared__ float pooled[HID];
    __shared__ float x[512];
    const int b = blockIdx.x;
    const int tid = threadIdx.x;
    const float* hp = h + (size_t)b * SEQ * HID;

    for (int j = tid; j < HID; j += 512) pooled[j] = hp[j];
    __syncthreads();
    {
        float acc = b1[tid];
        for (int k = 0; k < HID; k++) acc = fmaf(pooled[k], w1[(size_t)k * 512 + tid], acc);
        x[tid] = fmaxf(acc, 0.f);
    }
    __syncthreads();
    if (tid < NCLS) {
        float acc = b2[tid];
        for (int k = 0; k < 512; k++) acc = fmaf(x[k], w2[(size_t)k * NCLS + tid], acc);
        out[b * NCLS + tid] = acc;
    }
}

// ============================================================================
// kernel_launch
// ============================================================================
extern "C" void kernel_launch(void* const* d_in, const int* in_sizes, int n_in,
                              void* d_out, int out_size)
{
    (void)in_sizes; (void)n_in; (void)out_size;

    const int*   ids   = (const int*)  d_in[0];
    const int*   amask = (const int*)  d_in[1];
    const float* we    = (const float*)d_in[2];
    const float* pe    = (const float*)d_in[3];
    const float* te    = (const float*)d_in[4];
    const float* elg   = (const float*)d_in[5];
    const float* elb   = (const float*)d_in[6];
    const float* Wq    = (const float*)d_in[7];
    const float* bq    = (const float*)d_in[8];
    const float* Wk    = (const float*)d_in[9];
    const float* bk    = (const float*)d_in[10];
    const float* Wv    = (const float*)d_in[11];
    const float* bv    = (const float*)d_in[12];
    const float* Wo    = (const float*)d_in[13];
    const float* bo    = (const float*)d_in[14];
    const float* g1    = (const float*)d_in[15];
    const float* b1    = (const float*)d_in[16];
    const float* Wi    = (const float*)d_in[17];
    const float* bi    = (const float*)d_in[18];
    const float* Wo2   = (const float*)d_in[19];
    const float* bo2   = (const float*)d_in[20];
    const float* g2    = (const float*)d_in[21];
    const float* b2    = (const float*)d_in[22];
    const float* cw1   = (const float*)d_in[23];
    const float* cb1   = (const float*)d_in[24];
    const float* cw2   = (const float*)d_in[25];
    const float* cb2   = (const float*)d_in[26];
    float* out = (float*)d_out;

    float *h, *t, *q, *k, *v;
    __nv_bfloat16 *hhi, *hlo, *ahi, *alo, *fhi, *flo, *whi, *wlo;
    cudaGetSymbolAddress((void**)&h,   g_h);
    cudaGetSymbolAddress((void**)&t,   g_t);
    cudaGetSymbolAddress((void**)&q,   g_q);
    cudaGetSymbolAddress((void**)&k,   g_k);
    cudaGetSymbolAddress((void**)&v,   g_v);
    cudaGetSymbolAddress((void**)&hhi, g_hhi);
    cudaGetSymbolAddress((void**)&hlo, g_hlo);
    cudaGetSymbolAddress((void**)&ahi, g_ahi);
    cudaGetSymbolAddress((void**)&alo, g_alo);
    cudaGetSymbolAddress((void**)&fhi, g_fhi);
    cudaGetSymbolAddress((void**)&flo, g_flo);
    cudaGetSymbolAddress((void**)&whi, g_whi);
    cudaGetSymbolAddress((void**)&wlo, g_wlo);

    cudaFuncSetAttribute(tgemm<0>, cudaFuncAttributeMaxDynamicSharedMemorySize, DSMEM_BYTES);
    cudaFuncSetAttribute(tgemm<1>, cudaFuncAttributeMaxDynamicSharedMemorySize, DSMEM_BYTES);
    cudaFuncSetAttribute(tgemm<2>, cudaFuncAttributeMaxDynamicSharedMemorySize, DSMEM_BYTES);
    cudaFuncSetAttribute(tgemm<3>, cudaFuncAttributeMaxDynamicSharedMemorySize, DSMEM_BYTES);

    // ---- weight prep (transpose + bf16 split) ----
    {
        const dim3 bt(32, 8);
        const dim3 gHH(HID / 32, HID / 32);
        const dim3 gHF(FFD / 32, HID / 32);
        const dim3 gFH(HID / 32, FFD / 32);
        for (int l = 0; l < NLAYER; l++) {
            const size_t lw = (size_t)l * WLAYER;
            wprep<<<gHH, bt>>>(Wq  + (size_t)l*WSLOT_HH, whi + lw + 0*WSLOT_HH, wlo + lw + 0*WSLOT_HH, HID, HID);
            wprep<<<gHH, bt>>>(Wk  + (size_t)l*WSLOT_HH, whi + lw + 1*WSLOT_HH, wlo + lw + 1*WSLOT_HH, HID, HID);
            wprep<<<gHH, bt>>>(Wv  + (size_t)l*WSLOT_HH, whi + lw + 2*WSLOT_HH, wlo + lw + 2*WSLOT_HH, HID, HID);
            wprep<<<gHH, bt>>>(Wo  + (size_t)l*WSLOT_HH, whi + lw + 3*WSLOT_HH, wlo + lw + 3*WSLOT_HH, HID, HID);
            wprep<<<gHF, bt>>>(Wi  + (size_t)l*WSLOT_HF, whi + lw + 4*WSLOT_HH, wlo + lw + 4*WSLOT_HH, HID, FFD);
            wprep<<<gFH, bt>>>(Wo2 + (size_t)l*WSLOT_HF, whi + lw + 4*WSLOT_HH + WSLOT_HF,
                                                          wlo + lw + 4*WSLOT_HH + WSLOT_HF, FFD, HID);
        }
    }

    embed_ln_kernel<<<MTOK, 256>>>(ids, we, pe, te, elg, elb, h, hhi, hlo);

    const dim3 g768 (HID / 128, MTOK / 128);
    const dim3 g3072(FFD / 128, MTOK / 128);
    const dim3 ga(NCHUNK, NHEAD, BATCH);
    const float qscale = 0.125f;

    for (int l = 0; l < NLAYER; l++) {
        const size_t lw = (size_t)l * WLAYER;
        const __nv_bfloat16* wqh = whi + lw + 0*WSLOT_HH, *wql = wlo + lw + 0*WSLOT_HH;
        const __nv_bfloat16* wkh = whi + lw + 1*WSLOT_HH, *wkl = wlo + lw + 1*WSLOT_HH;
        const __nv_bfloat16* wvh = whi + lw + 2*WSLOT_HH, *wvl = wlo + lw + 2*WSLOT_HH;
        const __nv_bfloat16* woh = whi + lw + 3*WSLOT_HH, *wol = wlo + lw + 3*WSLOT_HH;
        const __nv_bfloat16* wih = whi + lw + 4*WSLOT_HH, *wil = wlo + lw + 4*WSLOT_HH;
        const __nv_bfloat16* w2h = whi + lw + 4*WSLOT_HH + WSLOT_HF;
        const __nv_bfloat16* w2l = wlo + lw + 4*WSLOT_HH + WSLOT_HF;

        tgemm<1><<<g768, 256, DSMEM_BYTES>>>(hhi, hlo, wqh, wql, bq + l*HID, nullptr, q, nullptr, nullptr, HID, HID, qscale);
        tgemm<0><<<g768, 256, DSMEM_BYTES>>>(hhi, hlo, wkh, wkl, bk + l*HID, nullptr, k, nullptr, nullptr, HID, HID, 1.f);
        tgemm<0><<<g768, 256, DSMEM_BYTES>>>(hhi, hlo, wvh, wvl, bv + l*HID, nullptr, v, nullptr, nullptr, HID, HID, 1.f);

        attn_kernel<<<ga, 256>>>(q, k, v, amask, ahi, alo);

        tgemm<2><<<g768, 256, DSMEM_BYTES>>>(ahi, alo, woh, wol, bo + l*HID, h, t, nullptr, nullptr, HID, HID, 1.f);
        ln_kernel<<<MTOK, 256>>>(t, g1 + l*HID, b1 + l*HID, h, hhi, hlo);

        tgemm<3><<<g3072, 256, DSMEM_BYTES>>>(hhi, hlo, wih, wil, bi + l*FFD, nullptr, nullptr, fhi, flo, HID, FFD, 1.f);
        tgemm<2><<<g768, 256, DSMEM_BYTES>>>(fhi, flo, w2h, w2l, bo2 + l*HID, h, t, nullptr, nullptr, FFD, HID, 1.f);
        ln_kernel<<<MTOK, 256>>>(t, g2 + l*HID, b2 + l*HID, h, hhi, hlo);
    }

    cls_kernel<<<BATCH, 512>>>(h, cw1, cb1, cw2, cb2, out);
}

// round 13
// speedup vs baseline: 2.0663x; 1.0344x over previous
#include <cuda_runtime.h>
#include <cuda_bf16.h>
#include <math.h>
#include <stdint.h>

// ---------------- problem constants ----------------
#define SEQ     4096
#define BATCH   2
#define HID     768
#define NHEAD   12
#define HD      64
#define NLAYER  12
#define FFD     3072
#define WIN     256
#define NCHUNK  16
#define MTOK    8192          // BATCH * SEQ
#define NCLS    43

#define WSLOT_HH 589824       // 768*768
#define WSLOT_HF 2359296      // 768*3072
#define WLAYER   7077888      // 4*HH + 2*HF

// ---------------- scratch (static device globals; allocation-free) ----------------
__device__ float g_h[MTOK*HID];
__device__ float g_t[MTOK*HID];
__device__ float g_q[MTOK*HID];
__device__ float g_k[MTOK*HID];
__device__ float g_v[MTOK*HID];
__device__ __nv_bfloat16 g_hhi[MTOK*HID];
__device__ __nv_bfloat16 g_hlo[MTOK*HID];
__device__ __nv_bfloat16 g_ahi[MTOK*HID];
__device__ __nv_bfloat16 g_alo[MTOK*HID];
__device__ __nv_bfloat16 g_fhi[MTOK*FFD];
__device__ __nv_bfloat16 g_flo[MTOK*FFD];
__device__ __nv_bfloat16 g_whi[(size_t)NLAYER*WLAYER];
__device__ __nv_bfloat16 g_wlo[(size_t)NLAYER*WLAYER];

// ---------------- PTX helpers (sm_80-class only: portable to sm_103 base) ----
__device__ __forceinline__ uint32_t smem_u32(const void* p) {
    uint32_t a;
    asm("{ .reg .u64 t; cvta.to.shared.u64 t, %1; cvt.u32.u64 %0, t; }" : "=r"(a) : "l"(p));
    return a;
}
__device__ __forceinline__ void cpasync16(uint32_t s, const void* g) {
    asm volatile("cp.async.cg.shared.global [%0], [%1], 16;" :: "r"(s), "l"(g));
}
__device__ __forceinline__ void cp_commit() {
    asm volatile("cp.async.commit_group;" ::: "memory");
}
__device__ __forceinline__ void cp_wait2() {
    asm volatile("cp.async.wait_group 2;" ::: "memory");
}
__device__ __forceinline__ void ldm_x4(uint32_t* r, uint32_t a) {
    asm volatile("ldmatrix.sync.aligned.m8n8.x4.shared.b16 {%0,%1,%2,%3}, [%4];"
        : "=r"(r[0]), "=r"(r[1]), "=r"(r[2]), "=r"(r[3]) : "r"(a));
}
__device__ __forceinline__ void mma16816(float* c, const uint32_t* a, const uint32_t* b) {
    asm volatile(
        "mma.sync.aligned.m16n8k16.row.col.f32.bf16.bf16.f32 "
        "{%0,%1,%2,%3}, {%4,%5,%6,%7}, {%8,%9}, {%0,%1,%2,%3};"
        : "+f"(c[0]), "+f"(c[1]), "+f"(c[2]), "+f"(c[3])
        : "r"(a[0]), "r"(a[1]), "r"(a[2]), "r"(a[3]), "r"(b[0]), "r"(b[1]));
}

__device__ __forceinline__ uint32_t swz(uint32_t b) { return b ^ ((b >> 3) & 0x70); }

__device__ __forceinline__ float gelu_exact(float x) {
    return 0.5f * x * (1.0f + erff(x * 0.70710678118654752f));
}
__device__ __forceinline__ uint32_t packbf2(float a, float b) {
    __nv_bfloat162 t = __floats2bfloat162_rn(a, b);
    return *reinterpret_cast<uint32_t*>(&t);
}
__device__ __forceinline__ float bf_hi(float x) {
    return __bfloat162float(__float2bfloat16(x));
}

// ============================================================================
// Weight prep: W[K][N] fp32  ->  hi/lo[N][K] bf16 (transpose + split)
// grid (N/32, K/32), block (32, 8)
// ============================================================================
__global__ void wprep(const float* __restrict__ W, __nv_bfloat16* __restrict__ hi,
                      __nv_bfloat16* __restrict__ lo, int K, int N)
{
    __shared__ float t[32][33];
    const int k0 = blockIdx.y * 32, n0 = blockIdx.x * 32;
    const int tx = threadIdx.x, ty = threadIdx.y;
#pragma unroll
    for (int i = 0; i < 4; i++)
        t[ty + i*8][tx] = W[(size_t)(k0 + ty + i*8) * N + n0 + tx];
    __syncthreads();
#pragma unroll
    for (int i = 0; i < 4; i++) {
        float x = t[tx][ty + i*8];
        __nv_bfloat16 h = __float2bfloat16(x);
        __nv_bfloat16 l = __float2bfloat16(x - __bfloat162float(h));
        size_t o = (size_t)(n0 + ty + i*8) * K + k0 + tx;
        hi[o] = h; lo[o] = l;
    }
}

// ============================================================================
// mma.sync bf16x3 GEMM: C[M,N] = A[M,K] @ B^T[N,K].
// A: Ahi/Alo [M][K] bf16 K-major; B: Bhi/Blo [N][K] bf16 K-major.
// 128x128 tile, BK=32, 3-stage cp.async pipeline, 256 threads (8 warps),
// 2 CTAs/SM. Smem rows are 128B: [hi k0..31 | lo k0..31] (SW128 swizzle).
// Warp tile 32m x 64n. 3 MMA passes: Ah*Bh + Ah*Bl + Al*Bh (fp32 accum).
// EPI: 0 fp32(+bias), 1 (+bias)*scale, 2 (+bias)+Res, 3 gelu -> bf16 hi/lo
// ============================================================================
#define NSTG        3
#define STG_BYTES   32768
#define DSMEM_BYTES (1024 + NSTG*STG_BYTES)
#define OFF_B       16384

template <int EPI>
__global__ __launch_bounds__(256, 2)
void tgemm(const __nv_bfloat16* __restrict__ Ahi, const __nv_bfloat16* __restrict__ Alo,
           const __nv_bfloat16* __restrict__ Bhi, const __nv_bfloat16* __restrict__ Blo,
           const float* __restrict__ bias, const float* __restrict__ Res,
           float* __restrict__ Cf, __nv_bfloat16* __restrict__ Chi, __nv_bfloat16* __restrict__ Clo,
           int K, int N, float scale)
{
    extern __shared__ char dsm[];
    char* sgen = (char*)((((uintptr_t)dsm) + 1023) & ~(uintptr_t)1023);
    const uint32_t sb = smem_u32(sgen);

    const int tid = threadIdx.x;
    const int wid = tid >> 5;
    const int lane = tid & 31;
    const int m0 = blockIdx.y * 128;
    const int n0 = blockIdx.x * 128;

    // ---- producer addressing (cp.async, 16B) ----
    // thread -> row (0..127), k-half (0..1). Each thread: 2x16B hi + 2x16B lo
    // for A, same for B. Row layout: [hi 64B | lo 64B], SW128 swizzle.
    const int lrow  = tid >> 1;
    const int lhalf = tid & 1;
    const size_t aoff = (size_t)(m0 + lrow) * K + lhalf * 16;
    const size_t boff = (size_t)(n0 + lrow) * K + lhalf * 16;
    uint32_t soh[2], sol[2];
#pragma unroll
    for (int g = 0; g < 2; g++) {
        soh[g] = swz((uint32_t)(lrow * 128 + lhalf * 32 + g * 16));
        sol[g] = swz((uint32_t)(lrow * 128 + 64 + lhalf * 32 + g * 16));
    }

    // ---- consumer (mma) lane addressing ----
    const int wm = wid & 3;              // 4 m-groups of 32
    const int wn = wid >> 2;             // 2 n-groups of 64
    const int xr = (lane & 7) * 16;      // swizzle XOR within 128B row
    const int aKoff = (lane & 16) ? 16 : 0;
    const int bKoff = (lane & 8)  ? 16 : 0;
    const int aRowIn = (lane & 7) + ((lane & 8)  ? 8 : 0);
    const int bRowIn = (lane & 7) + ((lane & 16) ? 8 : 0);
    uint32_t aRB[2], bRB[4];
#pragma unroll
    for (int mt = 0; mt < 2; mt++) aRB[mt] = (uint32_t)(wm*32 + mt*16 + aRowIn) * 128;
#pragma unroll
    for (int p = 0; p < 4; p++)    bRB[p]  = (uint32_t)(wn*64 + p*16 + bRowIn) * 128;

    float acc[2][8][4];
#pragma unroll
    for (int mt = 0; mt < 2; mt++)
#pragma unroll
        for (int nt = 0; nt < 8; nt++)
#pragma unroll
            for (int r = 0; r < 4; r++) acc[mt][nt][r] = 0.f;

    const int NC = K >> 5;               // chunks of 32

    auto issue = [&](int ck, int s) {
        const size_t kb = (size_t)ck * 32;
        const uint32_t st = sb + 1024 + s * STG_BYTES;
#pragma unroll
        for (int g = 0; g < 2; g++) {
            const size_t go = kb + g * 8;
            cpasync16(st + soh[g],         Ahi + aoff + go);
            cpasync16(st + sol[g],         Alo + aoff + go);
            cpasync16(st + OFF_B + soh[g], Bhi + boff + go);
            cpasync16(st + OFF_B + sol[g], Blo + boff + go);
        }
    };

    issue(0, 0); cp_commit();
    issue(1, 1); cp_commit();
    issue(2, 2); cp_commit();

    for (int ck = 0; ck < NC; ck++) {
        const int s = ck % NSTG;
        cp_wait2();
        __syncthreads();

        const uint32_t st = sb + 1024 + s * STG_BYTES;
#pragma unroll
        for (int ks = 0; ks < 2; ks++) {
            const uint32_t kh = (uint32_t)(ks * 32);
            uint32_t Ah[2][4], Al[2][4];
#pragma unroll
            for (int mt = 0; mt < 2; mt++) {
                ldm_x4(Ah[mt], st + aRB[mt] + (( kh      + aKoff) ^ xr));
                ldm_x4(Al[mt], st + aRB[mt] + ((64 + kh  + aKoff) ^ xr));
            }
#pragma unroll
            for (int p = 0; p < 4; p++) {
                uint32_t Bh[4], Bl[4];
                ldm_x4(Bh, st + OFF_B + bRB[p] + (( kh     + bKoff) ^ xr));
                ldm_x4(Bl, st + OFF_B + bRB[p] + ((64 + kh + bKoff) ^ xr));
#pragma unroll
                for (int mt = 0; mt < 2; mt++)
#pragma unroll
                    for (int hf = 0; hf < 2; hf++) {
                        float* c = acc[mt][p*2 + hf];
                        mma16816(c, Ah[mt], &Bh[hf*2]);
                        mma16816(c, Ah[mt], &Bl[hf*2]);
                        mma16816(c, Al[mt], &Bh[hf*2]);
                    }
            }
        }
        __syncthreads();
        if (ck + NSTG < NC) issue(ck + NSTG, s);
        cp_commit();
    }

    // ---- epilogue ----
    const int r0 = lane >> 2;            // 0..7
    const int cN = (lane & 3) * 2;
    const int mBase = m0 + wm * 32;
    const int nBase = n0 + wn * 64;

#pragma unroll
    for (int mt = 0; mt < 2; mt++) {
#pragma unroll
        for (int nt = 0; nt < 8; nt++) {
            const int n = nBase + nt * 8 + cN;
            const float bx = bias[n], by = bias[n + 1];
#pragma unroll
            for (int hf = 0; hf < 2; hf++) {
                const int m = mBase + mt * 16 + r0 + hf * 8;
                float vx = acc[mt][nt][hf*2 + 0] + bx;
                float vy = acc[mt][nt][hf*2 + 1] + by;
                if (EPI == 1) { vx *= scale; vy *= scale; }
                if (EPI == 2) {
                    const float2 rv = *(const float2*)(Res + (size_t)m * N + n);
                    vx += rv.x; vy += rv.y;
                }
                if (EPI == 3) {
                    vx = gelu_exact(vx); vy = gelu_exact(vy);
                    const size_t o = (size_t)m * N + n;
                    *(uint32_t*)(Chi + o) = packbf2(vx, vy);
                    *(uint32_t*)(Clo + o) = packbf2(vx - bf_hi(vx), vy - bf_hi(vy));
                } else {
                    float2 ov; ov.x = vx; ov.y = vy;
                    *(float2*)(Cf + (size_t)m * N + n) = ov;
                }
            }
        }
    }
}

// ============================================================================
// Embedding + LayerNorm -> fp32 h + bf16 hi/lo
// ============================================================================
__global__ void embed_ln_kernel(const int* __restrict__ ids,
                                const float* __restrict__ we, const float* __restrict__ pe,
                                const float* __restrict__ te, const float* __restrict__ g,
                                const float* __restrict__ be, float* __restrict__ out,
                                __nv_bfloat16* __restrict__ ohi, __nv_bfloat16* __restrict__ olo)
{
    __shared__ float red[256];
    const int row = blockIdx.x;
    const int s = row & (SEQ - 1);
    const int tid = threadIdx.x;
    const int id = ids[row];

    float x[3];
#pragma unroll
    for (int i = 0; i < 3; i++) {
        const int j = tid + i * 256;
        x[i] = we[(size_t)id * HID + j] + pe[(size_t)(s + 2) * HID + j] + te[j];
    }
    float sum = x[0] + x[1] + x[2];
    red[tid] = sum; __syncthreads();
    for (int st = 128; st > 0; st >>= 1) { if (tid < st) red[tid] += red[tid + st]; __syncthreads(); }
    const float mean = red[0] * (1.f / HID);
    __syncthreads();
    float vs = 0.f;
#pragma unroll
    for (int i = 0; i < 3; i++) { float dd = x[i] - mean; vs += dd * dd; }
    red[tid] = vs; __syncthreads();
    for (int st = 128; st > 0; st >>= 1) { if (tid < st) red[tid] += red[tid + st]; __syncthreads(); }
    const float rstd = rsqrtf(red[0] * (1.f / HID) + 1e-5f);

#pragma unroll
    for (int i = 0; i < 3; i++) {
        const int j = tid + i * 256;
        const float y = (x[i] - mean) * rstd * g[j] + be[j];
        const size_t o = (size_t)row * HID + j;
        out[o] = y;
        __nv_bfloat16 h = __float2bfloat16(y);
        ohi[o] = h;
        olo[o] = __float2bfloat16(y - __bfloat162float(h));
    }
}

// ============================================================================
// LayerNorm -> fp32 + bf16 hi/lo
// ============================================================================
__global__ void ln_kernel(const float* __restrict__ in, const float* __restrict__ g,
                          const float* __restrict__ be, float* __restrict__ out,
                          __nv_bfloat16* __restrict__ ohi, __nv_bfloat16* __restrict__ olo)
{
    __shared__ float red[256];
    const int row = blockIdx.x;
    const int tid = threadIdx.x;

    float x[3];
#pragma unroll
    for (int i = 0; i < 3; i++) x[i] = in[(size_t)row * HID + tid + i * 256];
    float sum = x[0] + x[1] + x[2];
    red[tid] = sum; __syncthreads();
    for (int st = 128; st > 0; st >>= 1) { if (tid < st) red[tid] += red[tid + st]; __syncthreads(); }
    const float mean = red[0] * (1.f / HID);
    __syncthreads();
    float vs = 0.f;
#pragma unroll
    for (int i = 0; i < 3; i++) { float dd = x[i] - mean; vs += dd * dd; }
    red[tid] = vs; __syncthreads();
    for (int st = 128; st > 0; st >>= 1) { if (tid < st) red[tid] += red[tid + st]; __syncthreads(); }
    const float rstd = rsqrtf(red[0] * (1.f / HID) + 1e-5f);

#pragma unroll
    for (int i = 0; i < 3; i++) {
        const int j = tid + i * 256;
        const float y = (x[i] - mean) * rstd * g[j] + be[j];
        const size_t o = (size_t)row * HID + j;
        out[o] = y;
        __nv_bfloat16 h = __float2bfloat16(y);
        ohi[o] = h;
        olo[o] = __float2bfloat16(y - __bfloat162float(h));
    }
}

// ============================================================================
// Sliding-window attention; output split to bf16 hi/lo.
// ============================================================================
__global__ __launch_bounds__(256, 1)
void attn_kernel(const float* __restrict__ qg, const float* __restrict__ kg,
                 const float* __restrict__ vg, const int* __restrict__ amask,
                 __nv_bfloat16* __restrict__ ohi, __nv_bfloat16* __restrict__ olo)
{
    __shared__ float ks [32][64];
    __shared__ float vsm[32][64];
    __shared__ int   kval[32];

    const int c  = blockIdx.x;
    const int hh = blockIdx.y;
    const int b  = blockIdx.z;
    const int r  = threadIdx.x;

    const size_t rowoff = ((size_t)(b * SEQ + c * WIN + r)) * HID + hh * HD;

    float qr[64];
#pragma unroll
    for (int i = 0; i < 16; i++) {
        float4 tq = *(const float4*)(qg + rowoff + i * 4);
        qr[4*i] = tq.x; qr[4*i+1] = tq.y; qr[4*i+2] = tq.z; qr[4*i+3] = tq.w;
    }
    float o[64];
#pragma unroll
    for (int i = 0; i < 64; i++) o[i] = 0.f;
    float mrun = -1e30f, lrun = 0.f;

    const int lr = r >> 3;
    const int lc = (r & 7) * 8;

    for (int t0 = 0; t0 < 3 * WIN; t0 += 32) {
        const int pos = (c - 1) * WIN + t0 + lr;
        const bool vld = (pos >= 0) && (pos < SEQ) && (amask[b * SEQ + pos] != 0);
        const float* kp = kg + ((size_t)(b * SEQ + pos)) * HID + hh * HD + lc;
        const float* vp = vg + ((size_t)(b * SEQ + pos)) * HID + hh * HD + lc;
        const float4 z = make_float4(0.f, 0.f, 0.f, 0.f);
        float4 ka = vld ? *(const float4*)(kp)     : z;
        float4 kb = vld ? *(const float4*)(kp + 4) : z;
        float4 va = vld ? *(const float4*)(vp)     : z;
        float4 vb = vld ? *(const float4*)(vp + 4) : z;

        __syncthreads();
        *(float4*)&ks [lr][lc]     = ka;
        *(float4*)&ks [lr][lc + 4] = kb;
        *(float4*)&vsm[lr][lc]     = va;
        *(float4*)&vsm[lr][lc + 4] = vb;
        if ((r & 7) == 0) kval[lr] = vld ? 1 : 0;
        __syncthreads();

        float sc[32];
        float tmax = -1e30f;
#pragma unroll
        for (int t = 0; t < 32; t++) {
            const int tk = t0 + t;
            float s_ = -1e30f;
            if ((tk >= r) && (tk <= r + 2 * WIN) && kval[t]) {
                s_ = 0.f;
#pragma unroll
                for (int i = 0; i < 16; i++) {
                    float4 kk = *(const float4*)&ks[t][4 * i];
                    s_ = fmaf(qr[4*i],   kk.x, s_);
                    s_ = fmaf(qr[4*i+1], kk.y, s_);
                    s_ = fmaf(qr[4*i+2], kk.z, s_);
                    s_ = fmaf(qr[4*i+3], kk.w, s_);
                }
            }
            sc[t] = s_;
            tmax = fmaxf(tmax, s_);
        }
        if (tmax > mrun) {
            const float corr = __expf(mrun - tmax);
            mrun = tmax;
            lrun *= corr;
#pragma unroll
            for (int i = 0; i < 64; i++) o[i] *= corr;
        }
#pragma unroll
        for (int t = 0; t < 32; t++) {
            if (sc[t] > -1e29f) {
                const float p = __expf(sc[t] - mrun);
                lrun += p;
#pragma unroll
                for (int i = 0; i < 16; i++) {
                    float4 vv = *(const float4*)&vsm[t][4 * i];
                    o[4*i]   = fmaf(p, vv.x, o[4*i]);
                    o[4*i+1] = fmaf(p, vv.y, o[4*i+1]);
                    o[4*i+2] = fmaf(p, vv.z, o[4*i+2]);
                    o[4*i+3] = fmaf(p, vv.w, o[4*i+3]);
                }
            }
        }
    }

    const float inv = 1.f / lrun;
#pragma unroll
    for (int i = 0; i < 8; i++) {
        float v[8];
#pragma unroll
        for (int j = 0; j < 8; j++) v[j] = o[i * 8 + j] * inv;
        uint4 hw, lw;
        hw.x = packbf2(v[0], v[1]); hw.y = packbf2(v[2], v[3]);
        hw.z = packbf2(v[4], v[5]); hw.w = packbf2(v[6], v[7]);
        float rr[8];
#pragma unroll
        for (int j = 0; j < 8; j++) rr[j] = v[j] - bf_hi(v[j]);
        lw.x = packbf2(rr[0], rr[1]); lw.y = packbf2(rr[2], rr[3]);
        lw.z = packbf2(rr[4], rr[5]); lw.w = packbf2(rr[6], rr[7]);
        *(uint4*)(ohi + rowoff + i * 8) = hw;
        *(uint4*)(olo + rowoff + i * 8) = lw;
    }
}

// ============================================================================
// Classifier head
// ============================================================================
__global__ void cls_kernel(const float* __restrict__ h,
                           const float* __restrict__ w1, const float* __restrict__ b1,
                           const float* __restrict__ w2, const float* __restrict__ b2,
                           float* __restrict__ out)
{
    __shared__ float pooled[HID];
    __shared__ float x[512];
    const int b = blockIdx.x;
    const int tid = threadIdx.x;
    const float* hp = h + (size_t)b * SEQ * HID;

    for (int j = tid; j < HID; j += 512) pooled[j] = hp[j];
    __syncthreads();
    {
        float acc = b1[tid];
        for (int k = 0; k < HID; k++) acc = fmaf(pooled[k], w1[(size_t)k * 512 + tid], acc);
        x[tid] = fmaxf(acc, 0.f);
    }
    __syncthreads();
    if (tid < NCLS) {
        float acc = b2[tid];
        for (int k = 0; k < 512; k++) acc = fmaf(x[k], w2[(size_t)k * NCLS + tid], acc);
        out[b * NCLS + tid] = acc;
    }
}

// ============================================================================
// kernel_launch
// ============================================================================
extern "C" void kernel_launch(void* const* d_in, const int* in_sizes, int n_in,
                              void* d_out, int out_size)
{
    (void)in_sizes; (void)n_in; (void)out_size;

    const int*   ids   = (const int*)  d_in[0];
    const int*   amask = (const int*)  d_in[1];
    const float* we    = (const float*)d_in[2];
    const float* pe    = (const float*)d_in[3];
    const float* te    = (const float*)d_in[4];
    const float* elg   = (const float*)d_in[5];
    const float* elb   = (const float*)d_in[6];
    const float* Wq    = (const float*)d_in[7];
    const float* bq    = (const float*)d_in[8];
    const float* Wk    = (const float*)d_in[9];
    const float* bk    = (const float*)d_in[10];
    const float* Wv    = (const float*)d_in[11];
    const float* bv    = (const float*)d_in[12];
    const float* Wo    = (const float*)d_in[13];
    const float* bo    = (const float*)d_in[14];
    const float* g1    = (const float*)d_in[15];
    const float* b1    = (const float*)d_in[16];
    const float* Wi    = (const float*)d_in[17];
    const float* bi    = (const float*)d_in[18];
    const float* Wo2   = (const float*)d_in[19];
    const float* bo2   = (const float*)d_in[20];
    const float* g2    = (const float*)d_in[21];
    const float* b2    = (const float*)d_in[22];
    const float* cw1   = (const float*)d_in[23];
    const float* cb1   = (const float*)d_in[24];
    const float* cw2   = (const float*)d_in[25];
    const float* cb2   = (const float*)d_in[26];
    float* out = (float*)d_out;

    float *h, *t, *q, *k, *v;
    __nv_bfloat16 *hhi, *hlo, *ahi, *alo, *fhi, *flo, *whi, *wlo;
    cudaGetSymbolAddress((void**)&h,   g_h);
    cudaGetSymbolAddress((void**)&t,   g_t);
    cudaGetSymbolAddress((void**)&q,   g_q);
    cudaGetSymbolAddress((void**)&k,   g_k);
    cudaGetSymbolAddress((void**)&v,   g_v);
    cudaGetSymbolAddress((void**)&hhi, g_hhi);
    cudaGetSymbolAddress((void**)&hlo, g_hlo);
    cudaGetSymbolAddress((void**)&ahi, g_ahi);
    cudaGetSymbolAddress((void**)&alo, g_alo);
    cudaGetSymbolAddress((void**)&fhi, g_fhi);
    cudaGetSymbolAddress((void**)&flo, g_flo);
    cudaGetSymbolAddress((void**)&whi, g_whi);
    cudaGetSymbolAddress((void**)&wlo, g_wlo);

    cudaFuncSetAttribute(tgemm<0>, cudaFuncAttributeMaxDynamicSharedMemorySize, DSMEM_BYTES);
    cudaFuncSetAttribute(tgemm<1>, cudaFuncAttributeMaxDynamicSharedMemorySize, DSMEM_BYTES);
    cudaFuncSetAttribute(tgemm<2>, cudaFuncAttributeMaxDynamicSharedMemorySize, DSMEM_BYTES);
    cudaFuncSetAttribute(tgemm<3>, cudaFuncAttributeMaxDynamicSharedMemorySize, DSMEM_BYTES);

    // ---- weight prep (transpose + bf16 split) ----
    {
        const dim3 bt(32, 8);
        const dim3 gHH(HID / 32, HID / 32);
        const dim3 gHF(FFD / 32, HID / 32);
        const dim3 gFH(HID / 32, FFD / 32);
        for (int l = 0; l < NLAYER; l++) {
            const size_t lw = (size_t)l * WLAYER;
            wprep<<<gHH, bt>>>(Wq  + (size_t)l*WSLOT_HH, whi + lw + 0*WSLOT_HH, wlo + lw + 0*WSLOT_HH, HID, HID);
            wprep<<<gHH, bt>>>(Wk  + (size_t)l*WSLOT_HH, whi + lw + 1*WSLOT_HH, wlo + lw + 1*WSLOT_HH, HID, HID);
            wprep<<<gHH, bt>>>(Wv  + (size_t)l*WSLOT_HH, whi + lw + 2*WSLOT_HH, wlo + lw + 2*WSLOT_HH, HID, HID);
            wprep<<<gHH, bt>>>(Wo  + (size_t)l*WSLOT_HH, whi + lw + 3*WSLOT_HH, wlo + lw + 3*WSLOT_HH, HID, HID);
            wprep<<<gHF, bt>>>(Wi  + (size_t)l*WSLOT_HF, whi + lw + 4*WSLOT_HH, wlo + lw + 4*WSLOT_HH, HID, FFD);
            wprep<<<gFH, bt>>>(Wo2 + (size_t)l*WSLOT_HF, whi + lw + 4*WSLOT_HH + WSLOT_HF,
                                                          wlo + lw + 4*WSLOT_HH + WSLOT_HF, FFD, HID);
        }
    }

    embed_ln_kernel<<<MTOK, 256>>>(ids, we, pe, te, elg, elb, h, hhi, hlo);

    const dim3 g768 (HID / 128, MTOK / 128);
    const dim3 g3072(FFD / 128, MTOK / 128);
    const dim3 ga(NCHUNK, NHEAD, BATCH);
    const float qscale = 0.125f;

    for (int l = 0; l < NLAYER; l++) {
        const size_t lw = (size_t)l * WLAYER;
        const __nv_bfloat16* wqh = whi + lw + 0*WSLOT_HH, *wql = wlo + lw + 0*WSLOT_HH;
        const __nv_bfloat16* wkh = whi + lw + 1*WSLOT_HH, *wkl = wlo + lw + 1*WSLOT_HH;
        const __nv_bfloat16* wvh = whi + lw + 2*WSLOT_HH, *wvl = wlo + lw + 2*WSLOT_HH;
        const __nv_bfloat16* woh = whi + lw + 3*WSLOT_HH, *wol = wlo + lw + 3*WSLOT_HH;
        const __nv_bfloat16* wih = whi + lw + 4*WSLOT_HH, *wil = wlo + lw + 4*WSLOT_HH;
        const __nv_bfloat16* w2h = whi + lw + 4*WSLOT_HH + WSLOT_HF;
        const __nv_bfloat16* w2l = wlo + lw + 4*WSLOT_HH + WSLOT_HF;

        tgemm<1><<<g768, 256, DSMEM_BYTES>>>(hhi, hlo, wqh, wql, bq + l*HID, nullptr, q, nullptr, nullptr, HID, HID, qscale);
        tgemm<0><<<g768, 256, DSMEM_BYTES>>>(hhi, hlo, wkh, wkl, bk + l*HID, nullptr, k, nullptr, nullptr, HID, HID, 1.f);
        tgemm<0><<<g768, 256, DSMEM_BYTES>>>(hhi, hlo, wvh, wvl, bv + l*HID, nullptr, v, nullptr, nullptr, HID, HID, 1.f);

        attn_kernel<<<ga, 256>>>(q, k, v, amask, ahi, alo);

        tgemm<2><<<g768, 256, DSMEM_BYTES>>>(ahi, alo, woh, wol, bo + l*HID, h, t, nullptr, nullptr, HID, HID, 1.f);
        ln_kernel<<<MTOK, 256>>>(t, g1 + l*HID, b1 + l*HID, h, hhi, hlo);

        tgemm<3><<<g3072, 256, DSMEM_BYTES>>>(hhi, hlo, wih, wil, bi + l*FFD, nullptr, nullptr, fhi, flo, HID, FFD, 1.f);
        tgemm<2><<<g768, 256, DSMEM_BYTES>>>(fhi, flo, w2h, w2l, bo2 + l*HID, h, t, nullptr, nullptr, FFD, HID, 1.f);
        ln_kernel<<<MTOK, 256>>>(t, g2 + l*HID, b2 + l*HID, h, hhi, hlo);
    }

    cls_kernel<<<BATCH, 512>>>(h, cw1, cb1, cw2, cb2, out);
}

// round 14
// speedup vs baseline: 2.9203x; 1.4133x over previous
#include <cuda_runtime.h>
#include <cuda_bf16.h>
#include <math.h>
#include <stdint.h>

// ---------------- problem constants ----------------
#define SEQ     4096
#define BATCH   2
#define HID     768
#define NHEAD   12
#define HD      64
#define NLAYER  12
#define FFD     3072
#define WIN     256
#define MTOK    8192          // BATCH * SEQ
#define NCLS    43

#define WSLOT_HH 589824       // 768*768
#define WSLOT_HF 2359296      // 768*3072
#define WLAYER   7077888      // 4*HH + 2*HF

// ---------------- scratch (static device globals; allocation-free) ----------------
__device__ float g_h[MTOK*HID];
__device__ float g_t[MTOK*HID];
__device__ __nv_bfloat16 g_hhi[MTOK*HID];
__device__ __nv_bfloat16 g_hlo[MTOK*HID];
__device__ __nv_bfloat16 g_qhi[MTOK*HID];
__device__ __nv_bfloat16 g_qlo[MTOK*HID];
__device__ __nv_bfloat16 g_khi[MTOK*HID];
__device__ __nv_bfloat16 g_klo[MTOK*HID];
__device__ __nv_bfloat16 g_vhi[MTOK*HID];
__device__ __nv_bfloat16 g_vlo[MTOK*HID];
__device__ __nv_bfloat16 g_ahi[MTOK*HID];
__device__ __nv_bfloat16 g_alo[MTOK*HID];
__device__ __nv_bfloat16 g_fhi[MTOK*FFD];
__device__ __nv_bfloat16 g_flo[MTOK*FFD];
__device__ __nv_bfloat16 g_whi[(size_t)NLAYER*WLAYER];
__device__ __nv_bfloat16 g_wlo[(size_t)NLAYER*WLAYER];

// ---------------- PTX helpers (sm_80-class only: portable to sm_103 base) ----
__device__ __forceinline__ uint32_t smem_u32(const void* p) {
    uint32_t a;
    asm("{ .reg .u64 t; cvta.to.shared.u64 t, %1; cvt.u32.u64 %0, t; }" : "=r"(a) : "l"(p));
    return a;
}
__device__ __forceinline__ void cpasync16(uint32_t s, const void* g) {
    asm volatile("cp.async.cg.shared.global [%0], [%1], 16;" :: "r"(s), "l"(g));
}
__device__ __forceinline__ void cp_commit() {
    asm volatile("cp.async.commit_group;" ::: "memory");
}
__device__ __forceinline__ void cp_wait1() {
    asm volatile("cp.async.wait_group 1;" ::: "memory");
}
__device__ __forceinline__ void cp_wait2() {
    asm volatile("cp.async.wait_group 2;" ::: "memory");
}
__device__ __forceinline__ void ldm_x4(uint32_t* r, uint32_t a) {
    asm volatile("ldmatrix.sync.aligned.m8n8.x4.shared.b16 {%0,%1,%2,%3}, [%4];"
        : "=r"(r[0]), "=r"(r[1]), "=r"(r[2]), "=r"(r[3]) : "r"(a));
}
__device__ __forceinline__ void ldm_x4_t(uint32_t* r, uint32_t a) {
    asm volatile("ldmatrix.sync.aligned.m8n8.x4.trans.shared.b16 {%0,%1,%2,%3}, [%4];"
        : "=r"(r[0]), "=r"(r[1]), "=r"(r[2]), "=r"(r[3]) : "r"(a));
}
__device__ __forceinline__ void mma16816(float* c, const uint32_t* a, const uint32_t* b) {
    asm volatile(
        "mma.sync.aligned.m16n8k16.row.col.f32.bf16.bf16.f32 "
        "{%0,%1,%2,%3}, {%4,%5,%6,%7}, {%8,%9}, {%0,%1,%2,%3};"
        : "+f"(c[0]), "+f"(c[1]), "+f"(c[2]), "+f"(c[3])
        : "r"(a[0]), "r"(a[1]), "r"(a[2]), "r"(a[3]), "r"(b[0]), "r"(b[1]));
}

__device__ __forceinline__ uint32_t swz(uint32_t b) { return b ^ ((b >> 3) & 0x70); }

__device__ __forceinline__ float gelu_exact(float x) {
    return 0.5f * x * (1.0f + erff(x * 0.70710678118654752f));
}
__device__ __forceinline__ uint32_t packbf2(float a, float b) {
    __nv_bfloat162 t = __floats2bfloat162_rn(a, b);
    return *reinterpret_cast<uint32_t*>(&t);
}
__device__ __forceinline__ float bf_hi(float x) {
    return __bfloat162float(__float2bfloat16(x));
}

// ============================================================================
// Weight prep: W[K][N] fp32 -> hi/lo[N][K] bf16 (transpose + split)
// ============================================================================
__global__ void wprep(const float* __restrict__ W, __nv_bfloat16* __restrict__ hi,
                      __nv_bfloat16* __restrict__ lo, int K, int N)
{
    __shared__ float t[32][33];
    const int k0 = blockIdx.y * 32, n0 = blockIdx.x * 32;
    const int tx = threadIdx.x, ty = threadIdx.y;
#pragma unroll
    for (int i = 0; i < 4; i++)
        t[ty + i*8][tx] = W[(size_t)(k0 + ty + i*8) * N + n0 + tx];
    __syncthreads();
#pragma unroll
    for (int i = 0; i < 4; i++) {
        float x = t[tx][ty + i*8];
        __nv_bfloat16 h = __float2bfloat16(x);
        __nv_bfloat16 l = __float2bfloat16(x - __bfloat162float(h));
        size_t o = (size_t)(n0 + ty + i*8) * K + k0 + tx;
        hi[o] = h; lo[o] = l;
    }
}

// ============================================================================
// mma.sync bf16x3 GEMM (unchanged core from R13).
// EPI: 2 (+bias)+Res -> fp32, 3 gelu -> bf16 hi/lo,
//      4 (+bias)*scale -> bf16 hi/lo, 5 (+bias) -> bf16 hi/lo
// ============================================================================
#define NSTG        3
#define STG_BYTES   32768
#define DSMEM_BYTES (1024 + NSTG*STG_BYTES)
#define OFF_B       16384

template <int EPI>
__global__ __launch_bounds__(256, 2)
void tgemm(const __nv_bfloat16* __restrict__ Ahi, const __nv_bfloat16* __restrict__ Alo,
           const __nv_bfloat16* __restrict__ Bhi, const __nv_bfloat16* __restrict__ Blo,
           const float* __restrict__ bias, const float* __restrict__ Res,
           float* __restrict__ Cf, __nv_bfloat16* __restrict__ Chi, __nv_bfloat16* __restrict__ Clo,
           int K, int N, float scale)
{
    extern __shared__ char dsm[];
    char* sgen = (char*)((((uintptr_t)dsm) + 1023) & ~(uintptr_t)1023);
    const uint32_t sb = smem_u32(sgen);

    const int tid = threadIdx.x;
    const int wid = tid >> 5;
    const int lane = tid & 31;
    const int m0 = blockIdx.y * 128;
    const int n0 = blockIdx.x * 128;

    const int lrow  = tid >> 1;
    const int lhalf = tid & 1;
    const size_t aoff = (size_t)(m0 + lrow) * K + lhalf * 16;
    const size_t boff = (size_t)(n0 + lrow) * K + lhalf * 16;
    uint32_t soh[2], sol[2];
#pragma unroll
    for (int g = 0; g < 2; g++) {
        soh[g] = swz((uint32_t)(lrow * 128 + lhalf * 32 + g * 16));
        sol[g] = swz((uint32_t)(lrow * 128 + 64 + lhalf * 32 + g * 16));
    }

    const int wm = wid & 3;
    const int wn = wid >> 2;
    const int xr = (lane & 7) * 16;
    const int aKoff = (lane & 16) ? 16 : 0;
    const int bKoff = (lane & 8)  ? 16 : 0;
    const int aRowIn = (lane & 7) + ((lane & 8)  ? 8 : 0);
    const int bRowIn = (lane & 7) + ((lane & 16) ? 8 : 0);
    uint32_t aRB[2], bRB[4];
#pragma unroll
    for (int mt = 0; mt < 2; mt++) aRB[mt] = (uint32_t)(wm*32 + mt*16 + aRowIn) * 128;
#pragma unroll
    for (int p = 0; p < 4; p++)    bRB[p]  = (uint32_t)(wn*64 + p*16 + bRowIn) * 128;

    float acc[2][8][4];
#pragma unroll
    for (int mt = 0; mt < 2; mt++)
#pragma unroll
        for (int nt = 0; nt < 8; nt++)
#pragma unroll
            for (int r = 0; r < 4; r++) acc[mt][nt][r] = 0.f;

    const int NC = K >> 5;

    auto issue = [&](int ck, int s) {
        const size_t kb = (size_t)ck * 32;
        const uint32_t st = sb + 1024 + s * STG_BYTES;
#pragma unroll
        for (int g = 0; g < 2; g++) {
            const size_t go = kb + g * 8;
            cpasync16(st + soh[g],         Ahi + aoff + go);
            cpasync16(st + sol[g],         Alo + aoff + go);
            cpasync16(st + OFF_B + soh[g], Bhi + boff + go);
            cpasync16(st + OFF_B + sol[g], Blo + boff + go);
        }
    };

    issue(0, 0); cp_commit();
    issue(1, 1); cp_commit();
    issue(2, 2); cp_commit();

    for (int ck = 0; ck < NC; ck++) {
        const int s = ck % NSTG;
        cp_wait2();
        __syncthreads();

        const uint32_t st = sb + 1024 + s * STG_BYTES;
#pragma unroll
        for (int ks = 0; ks < 2; ks++) {
            const uint32_t kh = (uint32_t)(ks * 32);
            uint32_t Ah[2][4], Al[2][4];
#pragma unroll
            for (int mt = 0; mt < 2; mt++) {
                ldm_x4(Ah[mt], st + aRB[mt] + (( kh      + aKoff) ^ xr));
                ldm_x4(Al[mt], st + aRB[mt] + ((64 + kh  + aKoff) ^ xr));
            }
#pragma unroll
            for (int p = 0; p < 4; p++) {
                uint32_t Bh[4], Bl[4];
                ldm_x4(Bh, st + OFF_B + bRB[p] + (( kh     + bKoff) ^ xr));
                ldm_x4(Bl, st + OFF_B + bRB[p] + ((64 + kh + bKoff) ^ xr));
#pragma unroll
                for (int mt = 0; mt < 2; mt++)
#pragma unroll
                    for (int hf = 0; hf < 2; hf++) {
                        float* c = acc[mt][p*2 + hf];
                        mma16816(c, Ah[mt], &Bh[hf*2]);
                        mma16816(c, Ah[mt], &Bl[hf*2]);
                        mma16816(c, Al[mt], &Bh[hf*2]);
                    }
            }
        }
        __syncthreads();
        if (ck + NSTG < NC) issue(ck + NSTG, s);
        cp_commit();
    }

    // ---- epilogue ----
    const int r0 = lane >> 2;
    const int cN = (lane & 3) * 2;
    const int mBase = m0 + wm * 32;
    const int nBase = n0 + wn * 64;

#pragma unroll
    for (int mt = 0; mt < 2; mt++) {
#pragma unroll
        for (int nt = 0; nt < 8; nt++) {
            const int n = nBase + nt * 8 + cN;
            const float bx = bias[n], by = bias[n + 1];
#pragma unroll
            for (int hf = 0; hf < 2; hf++) {
                const int m = mBase + mt * 16 + r0 + hf * 8;
                float vx = acc[mt][nt][hf*2 + 0] + bx;
                float vy = acc[mt][nt][hf*2 + 1] + by;
                if (EPI == 4) { vx *= scale; vy *= scale; }
                if (EPI == 2) {
                    const float2 rv = *(const float2*)(Res + (size_t)m * N + n);
                    vx += rv.x; vy += rv.y;
                    float2 ov; ov.x = vx; ov.y = vy;
                    *(float2*)(Cf + (size_t)m * N + n) = ov;
                } else {
                    if (EPI == 3) { vx = gelu_exact(vx); vy = gelu_exact(vy); }
                    const size_t o = (size_t)m * N + n;
                    *(uint32_t*)(Chi + o) = packbf2(vx, vy);
                    *(uint32_t*)(Clo + o) = packbf2(vx - bf_hi(vx), vy - bf_hi(vy));
                }
            }
        }
    }
}

// ============================================================================
// Flash attention on mma.sync, bf16x3 for both S=QK^T and O=PV.
// grid (32, NHEAD, BATCH), 256 threads (8 warps), 128 q-rows per CTA.
// Keys covered: [q0-256, q0+384) = 10 tiles of 64 (band |gk-gq|<=256).
// Q pre-scaled by 1/8 (EPI 4 in the Q GEMM).
// ============================================================================
#define ATT_NT   10
#define AQ_OFF   0
#define AQL_OFF  16384
#define AKV_OFF  32768     // + s*32768 : KH +0, KL +8192, VH +16384, VL +24576
#define AKM_OFF  98304     // + s*64
#define ATT_SMEM (1024 + 98432)

__global__ __launch_bounds__(256)
void attn_tc(const __nv_bfloat16* __restrict__ qhi, const __nv_bfloat16* __restrict__ qlo,
             const __nv_bfloat16* __restrict__ khi, const __nv_bfloat16* __restrict__ klo,
             const __nv_bfloat16* __restrict__ vhi, const __nv_bfloat16* __restrict__ vlo,
             const int* __restrict__ amask,
             __nv_bfloat16* __restrict__ ohi, __nv_bfloat16* __restrict__ olo)
{
    extern __shared__ char dsm[];
    char* sgen = (char*)((((uintptr_t)dsm) + 1023) & ~(uintptr_t)1023);
    const uint32_t sb = smem_u32(sgen);

    const int tid = threadIdx.x, wid = tid >> 5, lane = tid & 31;
    const int q0 = blockIdx.x * 128;
    const int hh = blockIdx.y, b = blockIdx.z;
    const size_t headoff = (size_t)hh * HD;
    const size_t brow = (size_t)b * SEQ;
    const int wrow = wid * 16;

    // ---- Q tile load (128 rows x 64 d, hi/lo) ----
    {
        const int row = tid >> 1;
        const int sg0 = (tid & 1) * 4;
        const size_t src = (brow + q0 + row) * HID + headoff;
#pragma unroll
        for (int g = 0; g < 4; g++) {
            const uint32_t d = swz((uint32_t)(row * 128 + (sg0 + g) * 16));
            cpasync16(sb + AQ_OFF  + d, qhi + src + (sg0 + g) * 8);
            cpasync16(sb + AQL_OFF + d, qlo + src + (sg0 + g) * 8);
        }
    }
    cp_commit();

    auto issueKV = [&](int it, int s) {
        const int kg = q0 - 256 + it * 64;
        const uint32_t kb = sb + AKV_OFF + s * 32768;
        const int row = tid >> 2;
        const int sg0 = (tid & 3) * 2;
        int gk = kg + row;
        int gkc = gk < 0 ? 0 : (gk >= SEQ ? SEQ - 1 : gk);
        const size_t src = (brow + gkc) * HID + headoff;
#pragma unroll
        for (int g = 0; g < 2; g++) {
            const uint32_t d = swz((uint32_t)(row * 128 + (sg0 + g) * 16));
            cpasync16(kb + 0     + d, khi + src + (sg0 + g) * 8);
            cpasync16(kb + 8192  + d, klo + src + (sg0 + g) * 8);
            cpasync16(kb + 16384 + d, vhi + src + (sg0 + g) * 8);
            cpasync16(kb + 24576 + d, vlo + src + (sg0 + g) * 8);
        }
        if (tid < 64) {
            const int gk2 = kg + tid;
            char ok = 0;
            if (gk2 >= 0 && gk2 < SEQ && amask[brow + gk2] != 0) ok = 1;
            sgen[AKM_OFF + s * 64 + tid] = ok;
        }
    };

    issueKV(0, 0); cp_commit();
    issueKV(1, 1); cp_commit();
    cp_wait2();                 // Q resident
    __syncthreads();

    // ---- Q fragments (A layout), hi/lo ----
    const int aRowIn = (lane & 7) + ((lane & 8) ? 8 : 0);
    const int aKoff = (lane & 16) ? 16 : 0;
    uint32_t Qh[4][4], Ql[4][4];
#pragma unroll
    for (int dk = 0; dk < 4; dk++) {
        const uint32_t adr = swz((uint32_t)((wrow + aRowIn) * 128 + dk * 32 + aKoff));
        ldm_x4(Qh[dk], sb + AQ_OFF  + adr);
        ldm_x4(Ql[dk], sb + AQL_OFF + adr);
    }

    const int bRowIn = (lane & 7) + ((lane & 16) ? 8 : 0);
    const int bKoff = (lane & 8) ? 16 : 0;
    const int rA = wrow + (lane >> 2);
    const int colBase = (lane & 3) * 2;
    const int vRowIn = (lane & 7) + ((lane & 8) ? 8 : 0);
    const int vColOff = ((lane & 16) ? 8 : 0);

    float o[8][4];
#pragma unroll
    for (int j = 0; j < 8; j++)
#pragma unroll
        for (int e = 0; e < 4; e++) o[j][e] = 0.f;
    float mA = -1e9f, mB = -1e9f, lA = 0.f, lB = 0.f;

    for (int it = 0; it < ATT_NT; it++) {
        const int s = it & 1;
        cp_wait1();             // tile it resident
        __syncthreads();

        const uint32_t kb = sb + AKV_OFF + s * 32768;
        const char* km = sgen + AKM_OFF + s * 64;
        const int kg = q0 - 256 + it * 64;

        // ---- scores S (16 x 64) per warp, 3-pass bf16 ----
        float sc[8][4];
#pragma unroll
        for (int j = 0; j < 8; j++)
#pragma unroll
            for (int e = 0; e < 4; e++) sc[j][e] = 0.f;

#pragma unroll
        for (int dk = 0; dk < 4; dk++) {
#pragma unroll
            for (int ng = 0; ng < 4; ng++) {
                uint32_t Bh[4], Bl[4];
                const uint32_t adr = swz((uint32_t)((ng*16 + bRowIn) * 128 + dk * 32 + bKoff));
                ldm_x4(Bh, kb + 0    + adr);
                ldm_x4(Bl, kb + 8192 + adr);
#pragma unroll
                for (int hf = 0; hf < 2; hf++) {
                    float* c = sc[ng*2 + hf];
                    mma16816(c, Qh[dk], &Bh[hf*2]);
                    mma16816(c, Qh[dk], &Bl[hf*2]);
                    mma16816(c, Ql[dk], &Bh[hf*2]);
                }
            }
        }

        // ---- mask + online softmax ----
        float vmA = -1e9f, vmB = -1e9f;
#pragma unroll
        for (int j = 0; j < 8; j++) {
#pragma unroll
            for (int e = 0; e < 4; e++) {
                const int col = j*8 + colBase + (e & 1);
                const int gk = kg + col;
                const int gq = q0 + ((e < 2) ? rA : (rA + 8));
                const bool ok = (km[col] != 0) && ((unsigned)(gk - gq + 256) <= 512u);
                const float s_ = ok ? sc[j][e] : -1e9f;
                sc[j][e] = s_;
                if (e < 2) vmA = fmaxf(vmA, s_); else vmB = fmaxf(vmB, s_);
            }
        }
        vmA = fmaxf(vmA, __shfl_xor_sync(0xffffffffu, vmA, 1));
        vmA = fmaxf(vmA, __shfl_xor_sync(0xffffffffu, vmA, 2));
        vmB = fmaxf(vmB, __shfl_xor_sync(0xffffffffu, vmB, 1));
        vmB = fmaxf(vmB, __shfl_xor_sync(0xffffffffu, vmB, 2));

        const float mnA = fmaxf(mA, vmA), mnB = fmaxf(mB, vmB);
        const float fA = __expf(mA - mnA), fB = __expf(mB - mnB);
        mA = mnA; mB = mnB;
        lA *= fA; lB *= fB;
#pragma unroll
        for (int j = 0; j < 8; j++) { o[j][0] *= fA; o[j][1] *= fA; o[j][2] *= fB; o[j][3] *= fB; }

        float sA = 0.f, sB = 0.f;
#pragma unroll
        for (int j = 0; j < 8; j++) {
#pragma unroll
            for (int e = 0; e < 4; e++) {
                const float p = __expf(sc[j][e] - ((e < 2) ? mA : mB));
                sc[j][e] = p;
                if (e < 2) sA += p; else sB += p;
            }
        }
        lA += sA; lB += sB;

        // ---- O += P @ V, 3-pass bf16 (P split in registers) ----
#pragma unroll
        for (int kc = 0; kc < 4; kc++) {
            uint32_t Ph[4], Pl[4];
            {
                const float p0 = sc[2*kc][0], p1 = sc[2*kc][1], p2 = sc[2*kc][2], p3 = sc[2*kc][3];
                const float r0 = sc[2*kc+1][0], r1 = sc[2*kc+1][1], r2 = sc[2*kc+1][2], r3 = sc[2*kc+1][3];
                Ph[0] = packbf2(p0, p1); Ph[1] = packbf2(p2, p3);
                Ph[2] = packbf2(r0, r1); Ph[3] = packbf2(r2, r3);
                Pl[0] = packbf2(p0 - bf_hi(p0), p1 - bf_hi(p1));
                Pl[1] = packbf2(p2 - bf_hi(p2), p3 - bf_hi(p3));
                Pl[2] = packbf2(r0 - bf_hi(r0), r1 - bf_hi(r1));
                Pl[3] = packbf2(r2 - bf_hi(r2), r3 - bf_hi(r3));
            }
#pragma unroll
            for (int ng = 0; ng < 4; ng++) {
                uint32_t Vh[4], Vl[4];
                const uint32_t adr = swz((uint32_t)((kc*16 + vRowIn) * 128 + (ng*16 + vColOff) * 2));
                ldm_x4_t(Vh, kb + 16384 + adr);
                ldm_x4_t(Vl, kb + 24576 + adr);
#pragma unroll
                for (int hf = 0; hf < 2; hf++) {
                    float* c = o[ng*2 + hf];
                    mma16816(c, Ph, &Vh[hf*2]);
                    mma16816(c, Ph, &Vl[hf*2]);
                    mma16816(c, Pl, &Vh[hf*2]);
                }
            }
        }

        __syncthreads();        // all warps done with buffer s before refill
        if (it + 2 < ATT_NT) { issueKV(it + 2, s); }
        cp_commit();
    }

    // ---- finalize: row sums, normalize, write bf16 hi/lo ----
    lA += __shfl_xor_sync(0xffffffffu, lA, 1);
    lA += __shfl_xor_sync(0xffffffffu, lA, 2);
    lB += __shfl_xor_sync(0xffffffffu, lB, 1);
    lB += __shfl_xor_sync(0xffffffffu, lB, 2);
    const float iA = 1.f / lA, iB = 1.f / lB;

#pragma unroll
    for (int j = 0; j < 8; j++) {
        const size_t oA = (brow + q0 + rA) * (size_t)HID + headoff + j*8 + colBase;
        const size_t oB = oA + (size_t)8 * HID;
        const float a0 = o[j][0] * iA, a1 = o[j][1] * iA;
        const float b0 = o[j][2] * iB, b1 = o[j][3] * iB;
        *(uint32_t*)(ohi + oA) = packbf2(a0, a1);
        *(uint32_t*)(olo + oA) = packbf2(a0 - bf_hi(a0), a1 - bf_hi(a1));
        *(uint32_t*)(ohi + oB) = packbf2(b0, b1);
        *(uint32_t*)(olo + oB) = packbf2(b0 - bf_hi(b0), b1 - bf_hi(b1));
    }
}

// ============================================================================
// Embedding + LayerNorm -> fp32 h + bf16 hi/lo
// ============================================================================
__global__ void embed_ln_kernel(const int* __restrict__ ids,
                                const float* __restrict__ we, const float* __restrict__ pe,
                                const float* __restrict__ te, const float* __restrict__ g,
                                const float* __restrict__ be, float* __restrict__ out,
                                __nv_bfloat16* __restrict__ ohi, __nv_bfloat16* __restrict__ olo)
{
    __shared__ float red[256];
    const int row = blockIdx.x;
    const int s = row & (SEQ - 1);
    const int tid = threadIdx.x;
    const int id = ids[row];

    float x[3];
#pragma unroll
    for (int i = 0; i < 3; i++) {
        const int j = tid + i * 256;
        x[i] = we[(size_t)id * HID + j] + pe[(size_t)(s + 2) * HID + j] + te[j];
    }
    float sum = x[0] + x[1] + x[2];
    red[tid] = sum; __syncthreads();
    for (int st = 128; st > 0; st >>= 1) { if (tid < st) red[tid] += red[tid + st]; __syncthreads(); }
    const float mean = red[0] * (1.f / HID);
    __syncthreads();
    float vs = 0.f;
#pragma unroll
    for (int i = 0; i < 3; i++) { float dd = x[i] - mean; vs += dd * dd; }
    red[tid] = vs; __syncthreads();
    for (int st = 128; st > 0; st >>= 1) { if (tid < st) red[tid] += red[tid + st]; __syncthreads(); }
    const float rstd = rsqrtf(red[0] * (1.f / HID) + 1e-5f);

#pragma unroll
    for (int i = 0; i < 3; i++) {
        const int j = tid + i * 256;
        const float y = (x[i] - mean) * rstd * g[j] + be[j];
        const size_t o = (size_t)row * HID + j;
        out[o] = y;
        __nv_bfloat16 h = __float2bfloat16(y);
        ohi[o] = h;
        olo[o] = __float2bfloat16(y - __bfloat162float(h));
    }
}

// ============================================================================
// LayerNorm -> fp32 + bf16 hi/lo
// ============================================================================
__global__ void ln_kernel(const float* __restrict__ in, const float* __restrict__ g,
                          const float* __restrict__ be, float* __restrict__ out,
                          __nv_bfloat16* __restrict__ ohi, __nv_bfloat16* __restrict__ olo)
{
    __shared__ float red[256];
    const int row = blockIdx.x;
    const int tid = threadIdx.x;

    float x[3];
#pragma unroll
    for (int i = 0; i < 3; i++) x[i] = in[(size_t)row * HID + tid + i * 256];
    float sum = x[0] + x[1] + x[2];
    red[tid] = sum; __syncthreads();
    for (int st = 128; st > 0; st >>= 1) { if (tid < st) red[tid] += red[tid + st]; __syncthreads(); }
    const float mean = red[0] * (1.f / HID);
    __syncthreads();
    float vs = 0.f;
#pragma unroll
    for (int i = 0; i < 3; i++) { float dd = x[i] - mean; vs += dd * dd; }
    red[tid] = vs; __syncthreads();
    for (int st = 128; st > 0; st >>= 1) { if (tid < st) red[tid] += red[tid + st]; __syncthreads(); }
    const float rstd = rsqrtf(red[0] * (1.f / HID) + 1e-5f);

#pragma unroll
    for (int i = 0; i < 3; i++) {
        const int j = tid + i * 256;
        const float y = (x[i] - mean) * rstd * g[j] + be[j];
        const size_t o = (size_t)row * HID + j;
        out[o] = y;
        __nv_bfloat16 h = __float2bfloat16(y);
        ohi[o] = h;
        olo[o] = __float2bfloat16(y - __bfloat162float(h));
    }
}

// ============================================================================
// Classifier head
// ============================================================================
__global__ void cls_kernel(const float* __restrict__ h,
                           const float* __restrict__ w1, const float* __restrict__ b1,
                           const float* __restrict__ w2, const float* __restrict__ b2,
                           float* __restrict__ out)
{
    __shared__ float pooled[HID];
    __shared__ float x[512];
    const int b = blockIdx.x;
    const int tid = threadIdx.x;
    const float* hp = h + (size_t)b * SEQ * HID;

    for (int j = tid; j < HID; j += 512) pooled[j] = hp[j];
    __syncthreads();
    {
        float acc = b1[tid];
        for (int k = 0; k < HID; k++) acc = fmaf(pooled[k], w1[(size_t)k * 512 + tid], acc);
        x[tid] = fmaxf(acc, 0.f);
    }
    __syncthreads();
    if (tid < NCLS) {
        float acc = b2[tid];
        for (int k = 0; k < 512; k++) acc = fmaf(x[k], w2[(size_t)k * NCLS + tid], acc);
        out[b * NCLS + tid] = acc;
    }
}

// ============================================================================
// kernel_launch
// ============================================================================
extern "C" void kernel_launch(void* const* d_in, const int* in_sizes, int n_in,
                              void* d_out, int out_size)
{
    (void)in_sizes; (void)n_in; (void)out_size;

    const int*   ids   = (const int*)  d_in[0];
    const int*   amask = (const int*)  d_in[1];
    const float* we    = (const float*)d_in[2];
    const float* pe    = (const float*)d_in[3];
    const float* te    = (const float*)d_in[4];
    const float* elg   = (const float*)d_in[5];
    const float* elb   = (const float*)d_in[6];
    const float* Wq    = (const float*)d_in[7];
    const float* bq    = (const float*)d_in[8];
    const float* Wk    = (const float*)d_in[9];
    const float* bk    = (const float*)d_in[10];
    const float* Wv    = (const float*)d_in[11];
    const float* bv    = (const float*)d_in[12];
    const float* Wo    = (const float*)d_in[13];
    const float* bo    = (const float*)d_in[14];
    const float* g1    = (const float*)d_in[15];
    const float* b1    = (const float*)d_in[16];
    const float* Wi    = (const float*)d_in[17];
    const float* bi    = (const float*)d_in[18];
    const float* Wo2   = (const float*)d_in[19];
    const float* bo2   = (const float*)d_in[20];
    const float* g2    = (const float*)d_in[21];
    const float* b2    = (const float*)d_in[22];
    const float* cw1   = (const float*)d_in[23];
    const float* cb1   = (const float*)d_in[24];
    const float* cw2   = (const float*)d_in[25];
    const float* cb2   = (const float*)d_in[26];
    float* out = (float*)d_out;

    float *h, *t;
    __nv_bfloat16 *hhi, *hlo, *qhi, *qlo, *khi, *klo, *vhi, *vlo;
    __nv_bfloat16 *ahi, *alo, *fhi, *flo, *whi, *wlo;
    cudaGetSymbolAddress((void**)&h,   g_h);
    cudaGetSymbolAddress((void**)&t,   g_t);
    cudaGetSymbolAddress((void**)&hhi, g_hhi);
    cudaGetSymbolAddress((void**)&hlo, g_hlo);
    cudaGetSymbolAddress((void**)&qhi, g_qhi);
    cudaGetSymbolAddress((void**)&qlo, g_qlo);
    cudaGetSymbolAddress((void**)&khi, g_khi);
    cudaGetSymbolAddress((void**)&klo, g_klo);
    cudaGetSymbolAddress((void**)&vhi, g_vhi);
    cudaGetSymbolAddress((void**)&vlo, g_vlo);
    cudaGetSymbolAddress((void**)&ahi, g_ahi);
    cudaGetSymbolAddress((void**)&alo, g_alo);
    cudaGetSymbolAddress((void**)&fhi, g_fhi);
    cudaGetSymbolAddress((void**)&flo, g_flo);
    cudaGetSymbolAddress((void**)&whi, g_whi);
    cudaGetSymbolAddress((void**)&wlo, g_wlo);

    cudaFuncSetAttribute(tgemm<2>, cudaFuncAttributeMaxDynamicSharedMemorySize, DSMEM_BYTES);
    cudaFuncSetAttribute(tgemm<3>, cudaFuncAttributeMaxDynamicSharedMemorySize, DSMEM_BYTES);
    cudaFuncSetAttribute(tgemm<4>, cudaFuncAttributeMaxDynamicSharedMemorySize, DSMEM_BYTES);
    cudaFuncSetAttribute(tgemm<5>, cudaFuncAttributeMaxDynamicSharedMemorySize, DSMEM_BYTES);
    cudaFuncSetAttribute(attn_tc,  cudaFuncAttributeMaxDynamicSharedMemorySize, ATT_SMEM);

    // ---- weight prep (transpose + bf16 split) ----
    {
        const dim3 bt(32, 8);
        const dim3 gHH(HID / 32, HID / 32);
        const dim3 gHF(FFD / 32, HID / 32);
        const dim3 gFH(HID / 32, FFD / 32);
        for (int l = 0; l < NLAYER; l++) {
            const size_t lw = (size_t)l * WLAYER;
            wprep<<<gHH, bt>>>(Wq  + (size_t)l*WSLOT_HH, whi + lw + 0*WSLOT_HH, wlo + lw + 0*WSLOT_HH, HID, HID);
            wprep<<<gHH, bt>>>(Wk  + (size_t)l*WSLOT_HH, whi + lw + 1*WSLOT_HH, wlo + lw + 1*WSLOT_HH, HID, HID);
            wprep<<<gHH, bt>>>(Wv  + (size_t)l*WSLOT_HH, whi + lw + 2*WSLOT_HH, wlo + lw + 2*WSLOT_HH, HID, HID);
            wprep<<<gHH, bt>>>(Wo  + (size_t)l*WSLOT_HH, whi + lw + 3*WSLOT_HH, wlo + lw + 3*WSLOT_HH, HID, HID);
            wprep<<<gHF, bt>>>(Wi  + (size_t)l*WSLOT_HF, whi + lw + 4*WSLOT_HH, wlo + lw + 4*WSLOT_HH, HID, FFD);
            wprep<<<gFH, bt>>>(Wo2 + (size_t)l*WSLOT_HF, whi + lw + 4*WSLOT_HH + WSLOT_HF,
                                                          wlo + lw + 4*WSLOT_HH + WSLOT_HF, FFD, HID);
        }
    }

    embed_ln_kernel<<<MTOK, 256>>>(ids, we, pe, te, elg, elb, h, hhi, hlo);

    const dim3 g768 (HID / 128, MTOK / 128);
    const dim3 g3072(FFD / 128, MTOK / 128);
    const dim3 ga(SEQ / 128, NHEAD, BATCH);     // (32, 12, 2)
    const float qscale = 0.125f;

    for (int l = 0; l < NLAYER; l++) {
        const size_t lw = (size_t)l * WLAYER;
        const __nv_bfloat16* wqh = whi + lw + 0*WSLOT_HH, *wql = wlo + lw + 0*WSLOT_HH;
        const __nv_bfloat16* wkh = whi + lw + 1*WSLOT_HH, *wkl = wlo + lw + 1*WSLOT_HH;
        const __nv_bfloat16* wvh = whi + lw + 2*WSLOT_HH, *wvl = wlo + lw + 2*WSLOT_HH;
        const __nv_bfloat16* woh = whi + lw + 3*WSLOT_HH, *wol = wlo + lw + 3*WSLOT_HH;
        const __nv_bfloat16* wih = whi + lw + 4*WSLOT_HH, *wil = wlo + lw + 4*WSLOT_HH;
        const __nv_bfloat16* w2h = whi + lw + 4*WSLOT_HH + WSLOT_HF;
        const __nv_bfloat16* w2l = wlo + lw + 4*WSLOT_HH + WSLOT_HF;

        tgemm<4><<<g768, 256, DSMEM_BYTES>>>(hhi, hlo, wqh, wql, bq + l*HID, nullptr, nullptr, qhi, qlo, HID, HID, qscale);
        tgemm<5><<<g768, 256, DSMEM_BYTES>>>(hhi, hlo, wkh, wkl, bk + l*HID, nullptr, nullptr, khi, klo, HID, HID, 1.f);
        tgemm<5><<<g768, 256, DSMEM_BYTES>>>(hhi, hlo, wvh, wvl, bv + l*HID, nullptr, nullptr, vhi, vlo, HID, HID, 1.f);

        attn_tc<<<ga, 256, ATT_SMEM>>>(qhi, qlo, khi, klo, vhi, vlo, amask, ahi, alo);

        tgemm<2><<<g768, 256, DSMEM_BYTES>>>(ahi, alo, woh, wol, bo + l*HID, h, t, nullptr, nullptr, HID, HID, 1.f);
        ln_kernel<<<MTOK, 256>>>(t, g1 + l*HID, b1 + l*HID, h, hhi, hlo);

        tgemm<3><<<g3072, 256, DSMEM_BYTES>>>(hhi, hlo, wih, wil, bi + l*FFD, nullptr, nullptr, fhi, flo, HID, FFD, 1.f);
        tgemm<2><<<g768, 256, DSMEM_BYTES>>>(fhi, flo, w2h, w2l, bo2 + l*HID, h, t, nullptr, nullptr, FFD, HID, 1.f);
        ln_kernel<<<MTOK, 256>>>(t, g2 + l*HID, b2 + l*HID, h, hhi, hlo);
    }

    cls_kernel<<<BATCH, 512>>>(h, cw1, cb1, cw2, cb2, out);
}

// round 17
// speedup vs baseline: 3.5178x; 1.2046x over previous
#include <cuda_runtime.h>
#include <cuda_bf16.h>
#include <cuda_fp16.h>
#include <math.h>
#include <stdint.h>

// ---------------- problem constants ----------------
#define SEQ     4096
#define BATCH   2
#define HID     768
#define NHEAD   12
#define HD      64
#define NLAYER  12
#define FFD     3072
#define WIN     256
#define MTOK    8192          // BATCH * SEQ
#define NCLS    43

#define WSLOT_HH 589824       // 768*768
#define WSLOT_HF 2359296      // 768*3072
#define WLAYER   7077888      // 4*HH + 2*HF

// ---------------- scratch (static device globals; allocation-free) ----------------
__device__ float g_h[MTOK*HID];
__device__ float g_t[MTOK*HID];
__device__ __half g_x16[MTOK*HID];      // LN output fp16 (GEMM A)
__device__ __half g_a16[MTOK*HID];      // attention output fp16 (GEMM A)
__device__ __half g_f16[MTOK*FFD];      // GELU output fp16 (GEMM A)
__device__ __half g_w16[(size_t)NLAYER*WLAYER];   // weights fp16 [N][K]
__device__ __nv_bfloat16 g_qhi[MTOK*HID];
__device__ __nv_bfloat16 g_qlo[MTOK*HID];
__device__ __nv_bfloat16 g_khi[MTOK*HID];
__device__ __nv_bfloat16 g_klo[MTOK*HID];
__device__ __nv_bfloat16 g_vhi[MTOK*HID];
__device__ __nv_bfloat16 g_vlo[MTOK*HID];

// ---------------- PTX helpers (sm_80-class only: portable to sm_103 base) ----
__device__ __forceinline__ uint32_t smem_u32(const void* p) {
    uint32_t a;
    asm("{ .reg .u64 t; cvta.to.shared.u64 t, %1; cvt.u32.u64 %0, t; }" : "=r"(a) : "l"(p));
    return a;
}
__device__ __forceinline__ void cpasync16(uint32_t s, const void* g) {
    asm volatile("cp.async.cg.shared.global [%0], [%1], 16;" :: "r"(s), "l"(g));
}
__device__ __forceinline__ void cp_commit() {
    asm volatile("cp.async.commit_group;" ::: "memory");
}
__device__ __forceinline__ void cp_wait1() {
    asm volatile("cp.async.wait_group 1;" ::: "memory");
}
__device__ __forceinline__ void cp_wait2() {
    asm volatile("cp.async.wait_group 2;" ::: "memory");
}
__device__ __forceinline__ void ldm_x4(uint32_t* r, uint32_t a) {
    asm volatile("ldmatrix.sync.aligned.m8n8.x4.shared.b16 {%0,%1,%2,%3}, [%4];"
        : "=r"(r[0]), "=r"(r[1]), "=r"(r[2]), "=r"(r[3]) : "r"(a));
}
__device__ __forceinline__ void ldm_x4_t(uint32_t* r, uint32_t a) {
    asm volatile("ldmatrix.sync.aligned.m8n8.x4.trans.shared.b16 {%0,%1,%2,%3}, [%4];"
        : "=r"(r[0]), "=r"(r[1]), "=r"(r[2]), "=r"(r[3]) : "r"(a));
}
// bf16 mma (attention)
__device__ __forceinline__ void mma16816(float* c, const uint32_t* a, const uint32_t* b) {
    asm volatile(
        "mma.sync.aligned.m16n8k16.row.col.f32.bf16.bf16.f32 "
        "{%0,%1,%2,%3}, {%4,%5,%6,%7}, {%8,%9}, {%0,%1,%2,%3};"
        : "+f"(c[0]), "+f"(c[1]), "+f"(c[2]), "+f"(c[3])
        : "r"(a[0]), "r"(a[1]), "r"(a[2]), "r"(a[3]), "r"(b[0]), "r"(b[1]));
}
// fp16 mma (dense GEMMs)
__device__ __forceinline__ void mma16816h(float* c, const uint32_t* a, const uint32_t* b) {
    asm volatile(
        "mma.sync.aligned.m16n8k16.row.col.f32.f16.f16.f32 "
        "{%0,%1,%2,%3}, {%4,%5,%6,%7}, {%8,%9}, {%0,%1,%2,%3};"
        : "+f"(c[0]), "+f"(c[1]), "+f"(c[2]), "+f"(c[3])
        : "r"(a[0]), "r"(a[1]), "r"(a[2]), "r"(a[3]), "r"(b[0]), "r"(b[1]));
}

__device__ __forceinline__ uint32_t swz(uint32_t b) { return b ^ ((b >> 3) & 0x70); }

__device__ __forceinline__ float gelu_exact(float x) {
    return 0.5f * x * (1.0f + erff(x * 0.70710678118654752f));
}
__device__ __forceinline__ uint32_t packbf2(float a, float b) {
    __nv_bfloat162 t = __floats2bfloat162_rn(a, b);
    return *reinterpret_cast<uint32_t*>(&t);
}
__device__ __forceinline__ uint32_t packh2(float a, float b) {
    __half2 t = __floats2half2_rn(a, b);
    return *reinterpret_cast<uint32_t*>(&t);
}
__device__ __forceinline__ float bf_hi(float x) {
    return __bfloat162float(__float2bfloat16(x));
}

// ============================================================================
// Weight prep: W[K][N] fp32 -> fp16 [N][K] (transpose + convert)
// ============================================================================
__global__ void wprep(const float* __restrict__ W, __half* __restrict__ o16,
                      int K, int N)
{
    __shared__ float t[32][33];
    const int k0 = blockIdx.y * 32, n0 = blockIdx.x * 32;
    const int tx = threadIdx.x, ty = threadIdx.y;
#pragma unroll
    for (int i = 0; i < 4; i++)
        t[ty + i*8][tx] = W[(size_t)(k0 + ty + i*8) * N + n0 + tx];
    __syncthreads();
#pragma unroll
    for (int i = 0; i < 4; i++) {
        o16[(size_t)(n0 + ty + i*8) * K + k0 + tx] = __float2half_rn(t[tx][ty + i*8]);
    }
}

// ============================================================================
// fp16 single-pass mma.sync GEMM: C[M,N] = A[M,K] @ B^T[N,K], fp32 accum.
// 128x128 tile, BK=64, 3-stage cp.async pipeline, 256 threads, 2 CTAs/SM.
// EPI: 2 (+bias)+Res -> fp32 | 3 gelu -> fp16 | 4 (+bias)*scale -> bf16 hi/lo
//      | 5 (+bias) -> bf16 hi/lo
// ============================================================================
#define NSTG        3
#define STG_BYTES   32768
#define DSMEM_BYTES (1024 + NSTG*STG_BYTES)
#define OFF_B       16384

template <int EPI>
__global__ __launch_bounds__(256, 2)
void tgemm(const __half* __restrict__ A, const __half* __restrict__ B,
           const float* __restrict__ bias, const float* __restrict__ Res,
           float* __restrict__ Cf, __half* __restrict__ Ch,
           __nv_bfloat16* __restrict__ Chi, __nv_bfloat16* __restrict__ Clo,
           int K, int N, float scale)
{
    extern __shared__ char dsm[];
    char* sgen = (char*)((((uintptr_t)dsm) + 1023) & ~(uintptr_t)1023);
    const uint32_t sb = smem_u32(sgen);

    const int tid = threadIdx.x;
    const int wid = tid >> 5;
    const int lane = tid & 31;
    const int m0 = blockIdx.y * 128;
    const int n0 = blockIdx.x * 128;

    // ---- producer addressing: 128B rows (64 fp16 = BK), 64B per thread ----
    const int lrow  = tid >> 1;
    const int lhalf = tid & 1;
    const size_t aoff = (size_t)(m0 + lrow) * K + lhalf * 32;
    const size_t boff = (size_t)(n0 + lrow) * K + lhalf * 32;
    uint32_t so[4];
#pragma unroll
    for (int g = 0; g < 4; g++)
        so[g] = swz((uint32_t)(lrow * 128 + lhalf * 64 + g * 16));

    // ---- consumer lane addressing ----
    const int wm = wid & 3;
    const int wn = wid >> 2;
    const int xr = (lane & 7) * 16;
    const int aKoff = (lane & 16) ? 16 : 0;
    const int bKoff = (lane & 8)  ? 16 : 0;
    const int aRowIn = (lane & 7) + ((lane & 8)  ? 8 : 0);
    const int bRowIn = (lane & 7) + ((lane & 16) ? 8 : 0);
    uint32_t aRB[2], bRB[4];
#pragma unroll
    for (int mt = 0; mt < 2; mt++) aRB[mt] = (uint32_t)(wm*32 + mt*16 + aRowIn) * 128;
#pragma unroll
    for (int p = 0; p < 4; p++)    bRB[p]  = (uint32_t)(wn*64 + p*16 + bRowIn) * 128;

    float acc[2][8][4];
#pragma unroll
    for (int mt = 0; mt < 2; mt++)
#pragma unroll
        for (int nt = 0; nt < 8; nt++)
#pragma unroll
            for (int r = 0; r < 4; r++) acc[mt][nt][r] = 0.f;

    const int NC = K >> 6;               // chunks of 64

    auto issue = [&](int ck, int s) {
        const size_t kb = (size_t)ck * 64;
        const uint32_t st = sb + 1024 + s * STG_BYTES;
#pragma unroll
        for (int g = 0; g < 4; g++) {
            const size_t go = kb + g * 8;
            cpasync16(st + so[g],         A + aoff + go);
            cpasync16(st + OFF_B + so[g], B + boff + go);
        }
    };

    issue(0, 0); cp_commit();
    issue(1, 1); cp_commit();
    issue(2, 2); cp_commit();

    for (int ck = 0; ck < NC; ck++) {
        const int s = ck % NSTG;
        cp_wait2();
        __syncthreads();

        const uint32_t st = sb + 1024 + s * STG_BYTES;
#pragma unroll
        for (int ks = 0; ks < 4; ks++) {
            const uint32_t kbyt = (uint32_t)(ks * 32);
            uint32_t Ah[2][4];
#pragma unroll
            for (int mt = 0; mt < 2; mt++)
                ldm_x4(Ah[mt], st + aRB[mt] + ((kbyt + aKoff) ^ xr));
#pragma unroll
            for (int p = 0; p < 4; p++) {
                uint32_t Bh[4];
                ldm_x4(Bh, st + OFF_B + bRB[p] + ((kbyt + bKoff) ^ xr));
#pragma unroll
                for (int mt = 0; mt < 2; mt++)
#pragma unroll
                    for (int hf = 0; hf < 2; hf++)
                        mma16816h(acc[mt][p*2 + hf], Ah[mt], &Bh[hf*2]);
            }
        }
        __syncthreads();
        if (ck + NSTG < NC) issue(ck + NSTG, s);
        cp_commit();
    }

    // ---- epilogue ----
    const int r0 = lane >> 2;
    const int cN = (lane & 3) * 2;
    const int mBase = m0 + wm * 32;
    const int nBase = n0 + wn * 64;

#pragma unroll
    for (int mt = 0; mt < 2; mt++) {
#pragma unroll
        for (int nt = 0; nt < 8; nt++) {
            const int n = nBase + nt * 8 + cN;
            const float bx = bias[n], by = bias[n + 1];
#pragma unroll
            for (int hf = 0; hf < 2; hf++) {
                const int m = mBase + mt * 16 + r0 + hf * 8;
                float vx = acc[mt][nt][hf*2 + 0] + bx;
                float vy = acc[mt][nt][hf*2 + 1] + by;
                const size_t o = (size_t)m * N + n;
                if (EPI == 2) {
                    const float2 rv = *(const float2*)(Res + o);
                    float2 ov; ov.x = vx + rv.x; ov.y = vy + rv.y;
                    *(float2*)(Cf + o) = ov;
                } else if (EPI == 3) {
                    vx = gelu_exact(vx); vy = gelu_exact(vy);
                    *(uint32_t*)(Ch + o) = packh2(vx, vy);
                } else {
                    if (EPI == 4) { vx *= scale; vy *= scale; }
                    *(uint32_t*)(Chi + o) = packbf2(vx, vy);
                    *(uint32_t*)(Clo + o) = packbf2(vx - bf_hi(vx), vy - bf_hi(vy));
                }
            }
        }
    }
}

// ============================================================================
// Flash attention on mma.sync, bf16x3 (unchanged from R14 except fp16 output).
// grid (32, NHEAD, BATCH), 256 threads (8 warps), 128 q-rows per CTA.
// ============================================================================
#define ATT_NT   10
#define AQ_OFF   0
#define AQL_OFF  16384
#define AKV_OFF  32768     // + s*32768 : KH +0, KL +8192, VH +16384, VL +24576
#define AKM_OFF  98304     // + s*64
#define ATT_SMEM (1024 + 98432)

__global__ __launch_bounds__(256)
void attn_tc(const __nv_bfloat16* __restrict__ qhi, const __nv_bfloat16* __restrict__ qlo,
             const __nv_bfloat16* __restrict__ khi, const __nv_bfloat16* __restrict__ klo,
             const __nv_bfloat16* __restrict__ vhi, const __nv_bfloat16* __restrict__ vlo,
             const int* __restrict__ amask, __half* __restrict__ o16)
{
    extern __shared__ char dsm[];
    char* sgen = (char*)((((uintptr_t)dsm) + 1023) & ~(uintptr_t)1023);
    const uint32_t sb = smem_u32(sgen);

    const int tid = threadIdx.x, wid = tid >> 5, lane = tid & 31;
    const int q0 = blockIdx.x * 128;
    const int hh = blockIdx.y, b = blockIdx.z;
    const size_t headoff = (size_t)hh * HD;
    const size_t brow = (size_t)b * SEQ;
    const int wrow = wid * 16;

    {
        const int row = tid >> 1;
        const int sg0 = (tid & 1) * 4;
        const size_t src = (brow + q0 + row) * HID + headoff;
#pragma unroll
        for (int g = 0; g < 4; g++) {
            const uint32_t d = swz((uint32_t)(row * 128 + (sg0 + g) * 16));
            cpasync16(sb + AQ_OFF  + d, qhi + src + (sg0 + g) * 8);
            cpasync16(sb + AQL_OFF + d, qlo + src + (sg0 + g) * 8);
        }
    }
    cp_commit();

    auto issueKV = [&](int it, int s) {
        const int kg = q0 - 256 + it * 64;
        const uint32_t kb = sb + AKV_OFF + s * 32768;
        const int row = tid >> 2;
        const int sg0 = (tid & 3) * 2;
        int gk = kg + row;
        int gkc = gk < 0 ? 0 : (gk >= SEQ ? SEQ - 1 : gk);
        const size_t src = (brow + gkc) * HID + headoff;
#pragma unroll
        for (int g = 0; g < 2; g++) {
            const uint32_t d = swz((uint32_t)(row * 128 + (sg0 + g) * 16));
            cpasync16(kb + 0     + d, khi + src + (sg0 + g) * 8);
            cpasync16(kb + 8192  + d, klo + src + (sg0 + g) * 8);
            cpasync16(kb + 16384 + d, vhi + src + (sg0 + g) * 8);
            cpasync16(kb + 24576 + d, vlo + src + (sg0 + g) * 8);
        }
        if (tid < 64) {
            const int gk2 = kg + tid;
            char ok = 0;
            if (gk2 >= 0 && gk2 < SEQ && amask[brow + gk2] != 0) ok = 1;
            sgen[AKM_OFF + s * 64 + tid] = ok;
        }
    };

    issueKV(0, 0); cp_commit();
    issueKV(1, 1); cp_commit();
    cp_wait2();
    __syncthreads();

    const int aRowIn = (lane & 7) + ((lane & 8) ? 8 : 0);
    const int aKoff = (lane & 16) ? 16 : 0;
    uint32_t Qh[4][4], Ql[4][4];
#pragma unroll
    for (int dk = 0; dk < 4; dk++) {
        const uint32_t adr = swz((uint32_t)((wrow + aRowIn) * 128 + dk * 32 + aKoff));
        ldm_x4(Qh[dk], sb + AQ_OFF  + adr);
        ldm_x4(Ql[dk], sb + AQL_OFF + adr);
    }

    const int bRowIn = (lane & 7) + ((lane & 16) ? 8 : 0);
    const int bKoff = (lane & 8) ? 16 : 0;
    const int rA = wrow + (lane >> 2);
    const int colBase = (lane & 3) * 2;
    const int vRowIn = (lane & 7) + ((lane & 8) ? 8 : 0);
    const int vColOff = ((lane & 16) ? 8 : 0);

    float o[8][4];
#pragma unroll
    for (int j = 0; j < 8; j++)
#pragma unroll
        for (int e = 0; e < 4; e++) o[j][e] = 0.f;
    float mA = -1e9f, mB = -1e9f, lA = 0.f, lB = 0.f;

    for (int it = 0; it < ATT_NT; it++) {
        const int s = it & 1;
        cp_wait1();
        __syncthreads();

        const uint32_t kb = sb + AKV_OFF + s * 32768;
        const char* km = sgen + AKM_OFF + s * 64;
        const int kg = q0 - 256 + it * 64;

        float sc[8][4];
#pragma unroll
        for (int j = 0; j < 8; j++)
#pragma unroll
            for (int e = 0; e < 4; e++) sc[j][e] = 0.f;

#pragma unroll
        for (int dk = 0; dk < 4; dk++) {
#pragma unroll
            for (int ng = 0; ng < 4; ng++) {
                uint32_t Bh[4], Bl[4];
                const uint32_t adr = swz((uint32_t)((ng*16 + bRowIn) * 128 + dk * 32 + bKoff));
                ldm_x4(Bh, kb + 0    + adr);
                ldm_x4(Bl, kb + 8192 + adr);
#pragma unroll
                for (int hf = 0; hf < 2; hf++) {
                    float* c = sc[ng*2 + hf];
                    mma16816(c, Qh[dk], &Bh[hf*2]);
                    mma16816(c, Qh[dk], &Bl[hf*2]);
                    mma16816(c, Ql[dk], &Bh[hf*2]);
                }
            }
        }

        float vmA = -1e9f, vmB = -1e9f;
#pragma unroll
        for (int j = 0; j < 8; j++) {
#pragma unroll
            for (int e = 0; e < 4; e++) {
                const int col = j*8 + colBase + (e & 1);
                const int gk = kg + col;
                const int gq = q0 + ((e < 2) ? rA : (rA + 8));
                const bool ok = (km[col] != 0) && ((unsigned)(gk - gq + 256) <= 512u);
                const float s_ = ok ? sc[j][e] : -1e9f;
                sc[j][e] = s_;
                if (e < 2) vmA = fmaxf(vmA, s_); else vmB = fmaxf(vmB, s_);
            }
        }
        vmA = fmaxf(vmA, __shfl_xor_sync(0xffffffffu, vmA, 1));
        vmA = fmaxf(vmA, __shfl_xor_sync(0xffffffffu, vmA, 2));
        vmB = fmaxf(vmB, __shfl_xor_sync(0xffffffffu, vmB, 1));
        vmB = fmaxf(vmB, __shfl_xor_sync(0xffffffffu, vmB, 2));

        const float mnA = fmaxf(mA, vmA), mnB = fmaxf(mB, vmB);
        const float fA = __expf(mA - mnA), fB = __expf(mB - mnB);
        mA = mnA; mB = mnB;
        lA *= fA; lB *= fB;
#pragma unroll
        for (int j = 0; j < 8; j++) { o[j][0] *= fA; o[j][1] *= fA; o[j][2] *= fB; o[j][3] *= fB; }

        float sA = 0.f, sB = 0.f;
#pragma unroll
        for (int j = 0; j < 8; j++) {
#pragma unroll
            for (int e = 0; e < 4; e++) {
                const float p = __expf(sc[j][e] - ((e < 2) ? mA : mB));
                sc[j][e] = p;
                if (e < 2) sA += p; else sB += p;
            }
        }
        lA += sA; lB += sB;

#pragma unroll
        for (int kc = 0; kc < 4; kc++) {
            uint32_t Ph[4], Pl[4];
            {
                const float p0 = sc[2*kc][0], p1 = sc[2*kc][1], p2 = sc[2*kc][2], p3 = sc[2*kc][3];
                const float r0 = sc[2*kc+1][0], r1 = sc[2*kc+1][1], r2 = sc[2*kc+1][2], r3 = sc[2*kc+1][3];
                Ph[0] = packbf2(p0, p1); Ph[1] = packbf2(p2, p3);
                Ph[2] = packbf2(r0, r1); Ph[3] = packbf2(r2, r3);
                Pl[0] = packbf2(p0 - bf_hi(p0), p1 - bf_hi(p1));
                Pl[1] = packbf2(p2 - bf_hi(p2), p3 - bf_hi(p3));
                Pl[2] = packbf2(r0 - bf_hi(r0), r1 - bf_hi(r1));
                Pl[3] = packbf2(r2 - bf_hi(r2), r3 - bf_hi(r3));
            }
#pragma unroll
            for (int ng = 0; ng < 4; ng++) {
                uint32_t Vh[4], Vl[4];
                const uint32_t adr = swz((uint32_t)((kc*16 + vRowIn) * 128 + (ng*16 + vColOff) * 2));
                ldm_x4_t(Vh, kb + 16384 + adr);
                ldm_x4_t(Vl, kb + 24576 + adr);
#pragma unroll
                for (int hf = 0; hf < 2; hf++) {
                    float* c = o[ng*2 + hf];
                    mma16816(c, Ph, &Vh[hf*2]);
                    mma16816(c, Ph, &Vl[hf*2]);
                    mma16816(c, Pl, &Vh[hf*2]);
                }
            }
        }

        __syncthreads();
        if (it + 2 < ATT_NT) { issueKV(it + 2, s); }
        cp_commit();
    }

    lA += __shfl_xor_sync(0xffffffffu, lA, 1);
    lA += __shfl_xor_sync(0xffffffffu, lA, 2);
    lB += __shfl_xor_sync(0xffffffffu, lB, 1);
    lB += __shfl_xor_sync(0xffffffffu, lB, 2);
    const float iA = 1.f / lA, iB = 1.f / lB;

#pragma unroll
    for (int j = 0; j < 8; j++) {
        const size_t oA = (brow + q0 + rA) * (size_t)HID + headoff + j*8 + colBase;
        const size_t oB = oA + (size_t)8 * HID;
        *(uint32_t*)(o16 + oA) = packh2(o[j][0] * iA, o[j][1] * iA);
        *(uint32_t*)(o16 + oB) = packh2(o[j][2] * iB, o[j][3] * iB);
    }
}

// ============================================================================
// Embedding + LayerNorm -> fp32 h + fp16
// ============================================================================
__global__ void embed_ln_kernel(const int* __restrict__ ids,
                                const float* __restrict__ we, const float* __restrict__ pe,
                                const float* __restrict__ te, const float* __restrict__ g,
                                const float* __restrict__ be, float* __restrict__ out,
                                __half* __restrict__ o16)
{
    __shared__ float red[256];
    const int row = blockIdx.x;
    const int s = row & (SEQ - 1);
    const int tid = threadIdx.x;
    const int id = ids[row];

    float x[3];
#pragma unroll
    for (int i = 0; i < 3; i++) {
        const int j = tid + i * 256;
        x[i] = we[(size_t)id * HID + j] + pe[(size_t)(s + 2) * HID + j] + te[j];
    }
    float sum = x[0] + x[1] + x[2];
    red[tid] = sum; __syncthreads();
    for (int st = 128; st > 0; st >>= 1) { if (tid < st) red[tid] += red[tid + st]; __syncthreads(); }
    const float mean = red[0] * (1.f / HID);
    __syncthreads();
    float vs = 0.f;
#pragma unroll
    for (int i = 0; i < 3; i++) { float dd = x[i] - mean; vs += dd * dd; }
    red[tid] = vs; __syncthreads();
    for (int st = 128; st > 0; st >>= 1) { if (tid < st) red[tid] += red[tid + st]; __syncthreads(); }
    const float rstd = rsqrtf(red[0] * (1.f / HID) + 1e-5f);

#pragma unroll
    for (int i = 0; i < 3; i++) {
        const int j = tid + i * 256;
        const float y = (x[i] - mean) * rstd * g[j] + be[j];
        const size_t o = (size_t)row * HID + j;
        out[o] = y;
        o16[o] = __float2half_rn(y);
    }
}

// ============================================================================
// LayerNorm -> fp32 + fp16
// ============================================================================
__global__ void ln_kernel(const float* __restrict__ in, const float* __restrict__ g,
                          const float* __restrict__ be, float* __restrict__ out,
                          __half* __restrict__ o16)
{
    __shared__ float red[256];
    const int row = blockIdx.x;
    const int tid = threadIdx.x;

    float x[3];
#pragma unroll
    for (int i = 0; i < 3; i++) x[i] = in[(size_t)row * HID + tid + i * 256];
    float sum = x[0] + x[1] + x[2];
    red[tid] = sum; __syncthreads();
    for (int st = 128; st > 0; st >>= 1) { if (tid < st) red[tid] += red[tid + st]; __syncthreads(); }
    const float mean = red[0] * (1.f / HID);
    __syncthreads();
    float vs = 0.f;
#pragma unroll
    for (int i = 0; i < 3; i++) { float dd = x[i] - mean; vs += dd * dd; }
    red[tid] = vs; __syncthreads();
    for (int st = 128; st > 0; st >>= 1) { if (tid < st) red[tid] += red[tid + st]; __syncthreads(); }
    const float rstd = rsqrtf(red[0] * (1.f / HID) + 1e-5f);

#pragma unroll
    for (int i = 0; i < 3; i++) {
        const int j = tid + i * 256;
        const float y = (x[i] - mean) * rstd * g[j] + be[j];
        const size_t o = (size_t)row * HID + j;
        out[o] = y;
        o16[o] = __float2half_rn(y);
    }
}

// ============================================================================
// Classifier head
// ============================================================================
__global__ void cls_kernel(const float* __restrict__ h,
                           const float* __restrict__ w1, const float* __restrict__ b1,
                           const float* __restrict__ w2, const float* __restrict__ b2,
                           float* __restrict__ out)
{
    __shared__ float pooled[HID];
    __shared__ float x[512];
    const int b = blockIdx.x;
    const int tid = threadIdx.x;
    const float* hp = h + (size_t)b * SEQ * HID;

    for (int j = tid; j < HID; j += 512) pooled[j] = hp[j];
    __syncthreads();
    {
        float acc = b1[tid];
        for (int k = 0; k < HID; k++) acc = fmaf(pooled[k], w1[(size_t)k * 512 + tid], acc);
        x[tid] = fmaxf(acc, 0.f);
    }
    __syncthreads();
    if (tid < NCLS) {
        float acc = b2[tid];
        for (int k = 0; k < 512; k++) acc = fmaf(x[k], w2[(size_t)k * NCLS + tid], acc);
        out[b * NCLS + tid] = acc;
    }
}

// ============================================================================
// kernel_launch
// ============================================================================
extern "C" void kernel_launch(void* const* d_in, const int* in_sizes, int n_in,
                              void* d_out, int out_size)
{
    (void)in_sizes; (void)n_in; (void)out_size;

    const int*   ids   = (const int*)  d_in[0];
    const int*   amask = (const int*)  d_in[1];
    const float* we    = (const float*)d_in[2];
    const float* pe    = (const float*)d_in[3];
    const float* te    = (const float*)d_in[4];
    const float* elg   = (const float*)d_in[5];
    const float* elb   = (const float*)d_in[6];
    const float* Wq    = (const float*)d_in[7];
    const float* bq    = (const float*)d_in[8];
    const float* Wk    = (const float*)d_in[9];
    const float* bk    = (const float*)d_in[10];
    const float* Wv    = (const float*)d_in[11];
    const float* bv    = (const float*)d_in[12];
    const float* Wo    = (const float*)d_in[13];
    const float* bo    = (const float*)d_in[14];
    const float* g1    = (const float*)d_in[15];
    const float* b1    = (const float*)d_in[16];
    const float* Wi    = (const float*)d_in[17];
    const float* bi    = (const float*)d_in[18];
    const float* Wo2   = (const float*)d_in[19];
    const float* bo2   = (const float*)d_in[20];
    const float* g2    = (const float*)d_in[21];
    const float* b2    = (const float*)d_in[22];
    const float* cw1   = (const float*)d_in[23];
    const float* cb1   = (const float*)d_in[24];
    const float* cw2   = (const float*)d_in[25];
    const float* cb2   = (const float*)d_in[26];
    float* out = (float*)d_out;

    float *h, *t;
    __half *x16, *a16, *f16, *w16;
    __nv_bfloat16 *qhi, *qlo, *khi, *klo, *vhi, *vlo;
    cudaGetSymbolAddress((void**)&h,   g_h);
    cudaGetSymbolAddress((void**)&t,   g_t);
    cudaGetSymbolAddress((void**)&x16, g_x16);
    cudaGetSymbolAddress((void**)&a16, g_a16);
    cudaGetSymbolAddress((void**)&f16, g_f16);
    cudaGetSymbolAddress((void**)&w16, g_w16);
    cudaGetSymbolAddress((void**)&qhi, g_qhi);
    cudaGetSymbolAddress((void**)&qlo, g_qlo);
    cudaGetSymbolAddress((void**)&khi, g_khi);
    cudaGetSymbolAddress((void**)&klo, g_klo);
    cudaGetSymbolAddress((void**)&vhi, g_vhi);
    cudaGetSymbolAddress((void**)&vlo, g_vlo);

    cudaFuncSetAttribute(tgemm<2>, cudaFuncAttributeMaxDynamicSharedMemorySize, DSMEM_BYTES);
    cudaFuncSetAttribute(tgemm<3>, cudaFuncAttributeMaxDynamicSharedMemorySize, DSMEM_BYTES);
    cudaFuncSetAttribute(tgemm<4>, cudaFuncAttributeMaxDynamicSharedMemorySize, DSMEM_BYTES);
    cudaFuncSetAttribute(tgemm<5>, cudaFuncAttributeMaxDynamicSharedMemorySize, DSMEM_BYTES);
    cudaFuncSetAttribute(attn_tc,  cudaFuncAttributeMaxDynamicSharedMemorySize, ATT_SMEM);

    // ---- weight prep (transpose + fp16 convert) ----
    {
        const dim3 bt(32, 8);
        const dim3 gHH(HID / 32, HID / 32);
        const dim3 gHF(FFD / 32, HID / 32);
        const dim3 gFH(HID / 32, FFD / 32);
        for (int l = 0; l < NLAYER; l++) {
            const size_t lw = (size_t)l * WLAYER;
            wprep<<<gHH, bt>>>(Wq  + (size_t)l*WSLOT_HH, w16 + lw + 0*WSLOT_HH, HID, HID);
            wprep<<<gHH, bt>>>(Wk  + (size_t)l*WSLOT_HH, w16 + lw + 1*WSLOT_HH, HID, HID);
            wprep<<<gHH, bt>>>(Wv  + (size_t)l*WSLOT_HH, w16 + lw + 2*WSLOT_HH, HID, HID);
            wprep<<<gHH, bt>>>(Wo  + (size_t)l*WSLOT_HH, w16 + lw + 3*WSLOT_HH, HID, HID);
            wprep<<<gHF, bt>>>(Wi  + (size_t)l*WSLOT_HF, w16 + lw + 4*WSLOT_HH, HID, FFD);
            wprep<<<gFH, bt>>>(Wo2 + (size_t)l*WSLOT_HF, w16 + lw + 4*WSLOT_HH + WSLOT_HF, FFD, HID);
        }
    }

    embed_ln_kernel<<<MTOK, 256>>>(ids, we, pe, te, elg, elb, h, x16);

    const dim3 g768 (HID / 128, MTOK / 128);
    const dim3 g3072(FFD / 128, MTOK / 128);
    const dim3 ga(SEQ / 128, NHEAD, BATCH);
    const float qscale = 0.125f;

    for (int l = 0; l < NLAYER; l++) {
        const size_t lw = (size_t)l * WLAYER;
        const __half* wq16 = w16 + lw + 0*WSLOT_HH;
        const __half* wk16 = w16 + lw + 1*WSLOT_HH;
        const __half* wv16 = w16 + lw + 2*WSLOT_HH;
        const __half* wo16 = w16 + lw + 3*WSLOT_HH;
        const __half* wi16 = w16 + lw + 4*WSLOT_HH;
        const __half* w216 = w16 + lw + 4*WSLOT_HH + WSLOT_HF;

        tgemm<4><<<g768, 256, DSMEM_BYTES>>>(x16, wq16, bq + l*HID, nullptr, nullptr, nullptr, qhi, qlo, HID, HID, qscale);
        tgemm<5><<<g768, 256, DSMEM_BYTES>>>(x16, wk16, bk + l*HID, nullptr, nullptr, nullptr, khi, klo, HID, HID, 1.f);
        tgemm<5><<<g768, 256, DSMEM_BYTES>>>(x16, wv16, bv + l*HID, nullptr, nullptr, nullptr, vhi, vlo, HID, HID, 1.f);

        attn_tc<<<ga, 256, ATT_SMEM>>>(qhi, qlo, khi, klo, vhi, vlo, amask, a16);

        tgemm<2><<<g768, 256, DSMEM_BYTES>>>(a16, wo16, bo + l*HID, h, t, nullptr, nullptr, nullptr, HID, HID, 1.f);
        ln_kernel<<<MTOK, 256>>>(t, g1 + l*HID, b1 + l*HID, h, x16);

        tgemm<3><<<g3072, 256, DSMEM_BYTES>>>(x16, wi16, bi + l*FFD, nullptr, nullptr, f16, nullptr, nullptr, HID, FFD, 1.f);
        tgemm<2><<<g768, 256, DSMEM_BYTES>>>(f16, w216, bo2 + l*HID, h, t, nullptr, nullptr, nullptr, FFD, HID, 1.f);
        ln_kernel<<<MTOK, 256>>>(t, g2 + l*HID, b2 + l*HID, h, x16);
    }

    cls_kernel<<<BATCH, 512>>>(h, cw1, cb1, cw2, cb2, out);
}